// round 5
// baseline (speedup 1.0000x reference)
#include <cuda_runtime.h>
#include <cstdint>
#include <cstddef>

// RGAT 3-layer on GB300. Per layer:
//  prep:  fold a_src/a_dst into weights -> wsd [K][64]
//  gemm:  sd = X @ wsd  (per-node per-rel logits)   [3xTF32 mma]
//  gemm:  xw = X @ W[r] for all r                   [3xTF32 mma]
//  agg :  CSR(warp-per-dst) softmax + gather-sum, fused bias(+LN+ELU)
// 3xTF32: x = hi + lo (both tf32-representable); hi*hi + hi*lo + lo*hi
// recovers ~fp32 accuracy (drops only the ~2^-24 lo*lo term).

__device__ float g_xw[102400000];   // 50000*2048
__device__ float g_h [12800000];    // 50000*256
__device__ float g_sd[3200000];     // 50000*64
__device__ float g_wsd[16384];      // 256*64
__device__ int   g_cnt[50000];
__device__ int   g_rowptr[50001];
__device__ int   g_cur[50000];
__device__ int   g_psrc[800000];
__device__ int   g_pet [800000];
__device__ int   g_blk[64];
__device__ int   g_is64;

__device__ __forceinline__ float f2tf(float x) {
    uint32_t u; asm("cvt.rna.tf32.f32 %0, %1;" : "=r"(u) : "f"(x));
    return __uint_as_float(u);
}
__device__ __forceinline__ void mma_tf32(float c[4], const uint32_t a[4],
                                         uint32_t b0, uint32_t b1) {
    asm volatile(
        "mma.sync.aligned.m16n8k8.row.col.f32.tf32.tf32.f32 "
        "{%0,%1,%2,%3},{%4,%5,%6,%7},{%8,%9},{%0,%1,%2,%3};"
        : "+f"(c[0]), "+f"(c[1]), "+f"(c[2]), "+f"(c[3])
        : "r"(a[0]), "r"(a[1]), "r"(a[2]), "r"(a[3]), "r"(b0), "r"(b1));
}
__device__ __forceinline__ int ld_idx(const void* p, long long i, int is64) {
    return is64 ? (int)((const long long*)p)[i] : ((const int*)p)[i];
}

// ---------------- dtype detect + CSR build ----------------
__global__ void k_detect(const int* ei) {
    if (threadIdx.x == 0 && blockIdx.x == 0) {
        int z = 0;
        for (int i = 1; i < 64; i += 2) z += (ei[i] == 0);
        g_is64 = (z == 32);
    }
}
__global__ void k_zero(int N) {
    int i = blockIdx.x * blockDim.x + threadIdx.x;
    if (i < N) g_cnt[i] = 0;
}
__global__ void k_hist(const void* ei, int E) {
    int e = blockIdx.x * blockDim.x + threadIdx.x;
    if (e < E) atomicAdd(&g_cnt[ld_idx(ei, (long long)E + e, g_is64)], 1);
}
__global__ void k_scan1(int N) {
    __shared__ int sh[1024];
    int t = threadIdx.x, i = blockIdx.x * 1024 + t;
    int v = (i < N) ? g_cnt[i] : 0;
    int x = v; sh[t] = x; __syncthreads();
    for (int off = 1; off < 1024; off <<= 1) {
        int add = (t >= off) ? sh[t - off] : 0;
        __syncthreads();
        x += add; sh[t] = x;
        __syncthreads();
    }
    if (i < N) g_rowptr[i] = x - v;
    if (t == 1023) g_blk[blockIdx.x] = x;
}
__global__ void k_scan2(int nb) {
    if (threadIdx.x == 0 && blockIdx.x == 0) {
        int acc = 0;
        for (int b = 0; b < nb; ++b) { int t = g_blk[b]; g_blk[b] = acc; acc += t; }
    }
}
__global__ void k_scan3(int N, int E) {
    int i = blockIdx.x * blockDim.x + threadIdx.x;
    if (i < N) {
        int v = g_rowptr[i] + g_blk[i >> 10];
        g_rowptr[i] = v; g_cur[i] = v;
    }
    if (i == 0) g_rowptr[N] = E;
}
__global__ void k_scatter(const void* ei, const void* et, int E) {
    int e = blockIdx.x * blockDim.x + threadIdx.x;
    if (e >= E) return;
    int is64 = g_is64;
    int s = ld_idx(ei, e, is64);
    int d = ld_idx(ei, (long long)E + e, is64);
    int t = ld_idx(et, e, is64);
    int pos = atomicAdd(&g_cur[d], 1);
    g_psrc[pos] = s; g_pet[pos] = t;
}

// ---------------- fold attention vectors ----------------
// wsd[k][r*8+q]: q<4 -> head q src dot, q>=4 -> head q-4 dst dot; 0 for h>=H
__global__ void k_prep(const float* __restrict__ W, const float* __restrict__ as_,
                       const float* __restrict__ ad_, int K, int H, int C, int Wn) {
    int t = blockIdx.x * blockDim.x + threadIdx.x;
    if (t >= K * 64) return;
    int col = t & 63, k = t >> 6;
    int r = col >> 3, q = col & 7, h = q & 3;
    float acc = 0.f;
    if (h < H) {
        const float* av = ((q & 4) ? ad_ : as_) + h * C;
        const float* wp = W + ((size_t)r * K + k) * Wn + h * C;
        for (int c = 0; c < C; ++c) acc += wp[c] * av[c];
    }
    g_wsd[k * 64 + col] = acc;
}

// ---------------- 3xTF32 GEMM ----------------
// C[row][r*cRel + col] = A[row,:K] @ B[r][:K,:Ntot] (64-wide col block per blockIdx.y)
// dynamic smem: As_hi[128*36] As_lo[128*36] Bs_hi[32*72] Bs_lo[32*72] = 55296 B
#define GEMM_SMEM (size_t)((128 * 36 * 2 + 32 * 72 * 2) * sizeof(float))
__global__ __launch_bounds__(256) void k_gemm(
    const float* __restrict__ A, const float* __restrict__ B, float* __restrict__ C,
    int M, int K, int Ntot, int crs, int cRel) {
    extern __shared__ float smem[];
    float* AsH = smem;
    float* AsL = smem + 128 * 36;
    float* BsH = smem + 128 * 36 * 2;
    float* BsL = BsH + 32 * 72;

    const int tid = threadIdx.x;
    const int m0 = blockIdx.x * 128;
    const int nblks = Ntot >> 6;
    const int r = blockIdx.y / nblks;
    const int n0 = (blockIdx.y % nblks) << 6;
    const float* Bg = B + (size_t)r * K * Ntot;

    const int lane = tid & 31, wid = tid >> 5;
    const int gid = lane >> 2, tig = lane & 3;
    const int m_off = (wid & 3) * 32, n_off = (wid >> 2) * 32;

    float acc[2][4][4];
#pragma unroll
    for (int f = 0; f < 2; ++f)
#pragma unroll
        for (int n = 0; n < 4; ++n)
#pragma unroll
            for (int q = 0; q < 4; ++q) acc[f][n][q] = 0.f;

    const int nkt = K >> 5;
    for (int kt = 0; kt < nkt; ++kt) {
        __syncthreads();
        // A tile 128x32 -> hi/lo
#pragma unroll
        for (int i = 0; i < 4; ++i) {
            int slot = tid + i * 256;
            int row = slot >> 3, c4 = (slot & 7) * 4;
            float4 v = make_float4(0.f, 0.f, 0.f, 0.f);
            if (m0 + row < M)
                v = *(const float4*)(A + (size_t)(m0 + row) * K + kt * 32 + c4);
            float4 h, l;
            h.x = f2tf(v.x); l.x = f2tf(v.x - h.x);
            h.y = f2tf(v.y); l.y = f2tf(v.y - h.y);
            h.z = f2tf(v.z); l.z = f2tf(v.z - h.z);
            h.w = f2tf(v.w); l.w = f2tf(v.w - h.w);
            *(float4*)(AsH + row * 36 + c4) = h;
            *(float4*)(AsL + row * 36 + c4) = l;
        }
        // B tile 32x64 -> hi/lo
#pragma unroll
        for (int i = 0; i < 2; ++i) {
            int slot = tid + i * 256;
            int row = slot >> 4, c4 = (slot & 15) * 4;
            float4 v = *(const float4*)(Bg + (size_t)(kt * 32 + row) * Ntot + n0 + c4);
            float4 h, l;
            h.x = f2tf(v.x); l.x = f2tf(v.x - h.x);
            h.y = f2tf(v.y); l.y = f2tf(v.y - h.y);
            h.z = f2tf(v.z); l.z = f2tf(v.z - h.z);
            h.w = f2tf(v.w); l.w = f2tf(v.w - h.w);
            *(float4*)(BsH + row * 72 + c4) = h;
            *(float4*)(BsL + row * 72 + c4) = l;
        }
        __syncthreads();
#pragma unroll
        for (int ks = 0; ks < 4; ++ks) {
            uint32_t aH[2][4], aL[2][4];
#pragma unroll
            for (int f = 0; f < 2; ++f) {
                const int off = (m_off + f * 16 + gid) * 36 + ks * 8 + tig;
                aH[f][0] = __float_as_uint(AsH[off]);
                aH[f][1] = __float_as_uint(AsH[off + 8 * 36]);
                aH[f][2] = __float_as_uint(AsH[off + 4]);
                aH[f][3] = __float_as_uint(AsH[off + 8 * 36 + 4]);
                aL[f][0] = __float_as_uint(AsL[off]);
                aL[f][1] = __float_as_uint(AsL[off + 8 * 36]);
                aL[f][2] = __float_as_uint(AsL[off + 4]);
                aL[f][3] = __float_as_uint(AsL[off + 8 * 36 + 4]);
            }
#pragma unroll
            for (int nf = 0; nf < 4; ++nf) {
                const int boff = (ks * 8 + tig) * 72 + n_off + nf * 8 + gid;
                uint32_t bH0 = __float_as_uint(BsH[boff]);
                uint32_t bH1 = __float_as_uint(BsH[boff + 4 * 72]);
                uint32_t bL0 = __float_as_uint(BsL[boff]);
                uint32_t bL1 = __float_as_uint(BsL[boff + 4 * 72]);
                mma_tf32(acc[0][nf], aH[0], bH0, bH1);
                mma_tf32(acc[0][nf], aH[0], bL0, bL1);
                mma_tf32(acc[0][nf], aL[0], bH0, bH1);
                mma_tf32(acc[1][nf], aH[1], bH0, bH1);
                mma_tf32(acc[1][nf], aH[1], bL0, bL1);
                mma_tf32(acc[1][nf], aL[1], bH0, bH1);
            }
        }
    }
#pragma unroll
    for (int f = 0; f < 2; ++f) {
        int row = m0 + m_off + f * 16 + gid;
#pragma unroll
        for (int nf = 0; nf < 4; ++nf) {
            int col = n0 + n_off + nf * 8 + 2 * tig;
            if (row < M)
                *(float2*)(C + (size_t)row * crs + (size_t)r * cRel + col) =
                    make_float2(acc[f][nf][0], acc[f][nf][1]);
            if (row + 8 < M)
                *(float2*)(C + (size_t)(row + 8) * crs + (size_t)r * cRel + col) =
                    make_float2(acc[f][nf][2], acc[f][nf][3]);
        }
    }
}

// ---------------- aggregation ----------------
template <int H>
__device__ __forceinline__ void get_alpha(const float* __restrict__ sd,
                                          const float* __restrict__ ar,
                                          int dst, int s, int t, float* a) {
    if (H == 4) {
        float4 sv = *(const float4*)(sd + (size_t)s * 64 + t * 8);
        float4 dv = *(const float4*)(sd + (size_t)dst * 64 + t * 8 + 4);
        float4 av = *(const float4*)(ar + t * 4);
        a[0] = sv.x + dv.x + av.x; a[1] = sv.y + dv.y + av.y;
        a[2] = sv.z + dv.z + av.z; a[3] = sv.w + dv.w + av.w;
    } else {
        a[0] = sd[(size_t)s * 64 + t * 8] + sd[(size_t)dst * 64 + t * 8 + 4] + ar[t];
    }
#pragma unroll
    for (int h = 0; h < H; ++h) a[h] = a[h] > 0.f ? a[h] : 0.2f * a[h];
}

template <int CPL, bool LN>
__global__ __launch_bounds__(256) void k_agg(
    const float* __restrict__ xw, const float* __restrict__ sd,
    const float* __restrict__ ar, const float* __restrict__ bias,
    const float* __restrict__ gamma, const float* __restrict__ beta,
    float* __restrict__ out, int N, int xws, int rls) {
    constexpr int H = CPL * 32 / 64;     // 8->4, 2->1
    constexpr int OUT = CPL * 32;        // 256 or 64
    __shared__ float walpha[8][32][4];
    int w = (blockIdx.x * blockDim.x + threadIdx.x) >> 5;
    if (w >= N) return;
    int lane = threadIdx.x & 31, wl = threadIdx.x >> 5;
    int hh = (lane * CPL) >> 6;
    int beg = g_rowptr[w], end = g_rowptr[w + 1];

    float mx[H];
#pragma unroll
    for (int h = 0; h < H; ++h) mx[h] = -1e30f;
    for (int e = beg + lane; e < end; e += 32) {
        float a[H];
        get_alpha<H>(sd, ar, w, g_psrc[e], g_pet[e], a);
#pragma unroll
        for (int h = 0; h < H; ++h) mx[h] = fmaxf(mx[h], a[h]);
    }
#pragma unroll
    for (int h = 0; h < H; ++h)
#pragma unroll
        for (int o = 16; o; o >>= 1)
            mx[h] = fmaxf(mx[h], __shfl_xor_sync(0xffffffffu, mx[h], o));

    float sm[H];
#pragma unroll
    for (int h = 0; h < H; ++h) sm[h] = 0.f;
    for (int e = beg + lane; e < end; e += 32) {
        float a[H];
        get_alpha<H>(sd, ar, w, g_psrc[e], g_pet[e], a);
#pragma unroll
        for (int h = 0; h < H; ++h) sm[h] += __expf(a[h] - mx[h]);
    }
#pragma unroll
    for (int h = 0; h < H; ++h) {
#pragma unroll
        for (int o = 16; o; o >>= 1) sm[h] += __shfl_xor_sync(0xffffffffu, sm[h], o);
        sm[h] = 1.f / sm[h];
    }

    float acc[CPL];
#pragma unroll
    for (int c = 0; c < CPL; ++c) acc[c] = 0.f;

    for (int base = beg; base < end; base += 32) {
        int e = base + lane;
        int cnt = min(32, end - base);
        int sR = 0, tR = 0;
        if (e < end) {
            sR = g_psrc[e]; tR = g_pet[e];
            float a[H];
            get_alpha<H>(sd, ar, w, sR, tR, a);
#pragma unroll
            for (int h = 0; h < H; ++h)
                walpha[wl][lane][h] = __expf(a[h] - mx[h]) * sm[h];
        }
        __syncwarp();
        for (int j = 0; j < cnt; ++j) {
            int s = __shfl_sync(0xffffffffu, sR, j);
            int t = __shfl_sync(0xffffffffu, tR, j);
            float wv = walpha[wl][j][hh];
            const float* p = xw + (size_t)s * xws + t * rls + lane * CPL;
            if (CPL == 8) {
                float4 v0 = *(const float4*)p, v1 = *(const float4*)(p + 4);
                acc[0] += wv * v0.x; acc[1] += wv * v0.y;
                acc[2] += wv * v0.z; acc[3] += wv * v0.w;
                acc[4] += wv * v1.x; acc[5] += wv * v1.y;
                acc[6] += wv * v1.z; acc[7] += wv * v1.w;
            } else {
                float2 v = *(const float2*)p;
                acc[0] += wv * v.x; acc[1] += wv * v.y;
            }
        }
        __syncwarp();
    }

    if (LN) {
        float4 b0 = *(const float4*)(bias + lane * 8);
        float4 b1 = *(const float4*)(bias + lane * 8 + 4);
        acc[0] += b0.x; acc[1] += b0.y; acc[2] += b0.z; acc[3] += b0.w;
        acc[4] += b1.x; acc[5] += b1.y; acc[6] += b1.z; acc[7] += b1.w;
        float s1 = 0.f;
#pragma unroll
        for (int c = 0; c < CPL; ++c) s1 += acc[c];
#pragma unroll
        for (int o = 16; o; o >>= 1) s1 += __shfl_xor_sync(0xffffffffu, s1, o);
        float m = s1 / (float)OUT;
        float s2 = 0.f;
#pragma unroll
        for (int c = 0; c < CPL; ++c) { float d = acc[c] - m; s2 += d * d; }
#pragma unroll
        for (int o = 16; o; o >>= 1) s2 += __shfl_xor_sync(0xffffffffu, s2, o);
        float rstd = rsqrtf(s2 / (float)OUT + 1e-5f);
        float4 gA = *(const float4*)(gamma + lane * 8);
        float4 gB = *(const float4*)(gamma + lane * 8 + 4);
        float4 tA = *(const float4*)(beta + lane * 8);
        float4 tB = *(const float4*)(beta + lane * 8 + 4);
        float gm[8] = {gA.x, gA.y, gA.z, gA.w, gB.x, gB.y, gB.z, gB.w};
        float bt[8] = {tA.x, tA.y, tA.z, tA.w, tB.x, tB.y, tB.z, tB.w};
        float4 o0, o1;
#pragma unroll
        for (int c = 0; c < 8; ++c) {
            float y = gm[c] * (acc[c] - m) * rstd + bt[c];
            y = y > 0.f ? y : (expf(y) - 1.f);
            if (c < 4) (&o0.x)[c] = y; else (&o1.x)[c - 4] = y;
        }
        *(float4*)(out + (size_t)w * OUT + lane * 8) = o0;
        *(float4*)(out + (size_t)w * OUT + lane * 8 + 4) = o1;
    } else {
        out[(size_t)w * OUT + lane * 2] = acc[0] + bias[lane * 2];
        out[(size_t)w * OUT + lane * 2 + 1] = acc[1] + bias[lane * 2 + 1];
    }
}

// ---------------- launch ----------------
extern "C" void kernel_launch(void* const* d_in, const int* in_sizes, int n_in,
                              void* d_out, int out_size) {
    const float* x   = (const float*)d_in[0];
    const void*  ei  = d_in[1];
    const void*  et  = d_in[2];
    const float* W0  = (const float*)d_in[3];
    const float* as0 = (const float*)d_in[4];
    const float* ad0 = (const float*)d_in[5];
    const float* ar0 = (const float*)d_in[6];
    const float* bi0 = (const float*)d_in[7];
    const float* W1  = (const float*)d_in[8];
    const float* as1 = (const float*)d_in[9];
    const float* ad1 = (const float*)d_in[10];
    const float* ar1 = (const float*)d_in[11];
    const float* bi1 = (const float*)d_in[12];
    const float* W2  = (const float*)d_in[13];
    const float* as2 = (const float*)d_in[14];
    const float* ad2 = (const float*)d_in[15];
    const float* ar2 = (const float*)d_in[16];
    const float* bi2 = (const float*)d_in[17];
    const float* g0  = (const float*)d_in[18];
    const float* be0 = (const float*)d_in[19];
    const float* g1  = (const float*)d_in[20];
    const float* be1 = (const float*)d_in[21];

    const int N = in_sizes[0] / 128;        // 50000
    const int E = in_sizes[2];              // 800000
    float* out = (float*)d_out;

    float *xw, *h, *sd, *wsd;
    cudaGetSymbolAddress((void**)&xw, g_xw);
    cudaGetSymbolAddress((void**)&h, g_h);
    cudaGetSymbolAddress((void**)&sd, g_sd);
    cudaGetSymbolAddress((void**)&wsd, g_wsd);

    static int smem_set = 0;
    if (!smem_set) {
        cudaFuncSetAttribute(k_gemm, cudaFuncAttributeMaxDynamicSharedMemorySize,
                             (int)GEMM_SMEM);
        smem_set = 1;
    }

    const int MB = (N + 127) / 128;         // 391
    const int EB = (E + 255) / 256;
    const int NB = (N + 255) / 256;
    const int SB = (N + 1023) / 1024;

    // CSR build
    k_detect<<<1, 32>>>((const int*)ei);
    k_zero<<<NB, 256>>>(N);
    k_hist<<<EB, 256>>>(ei, E);
    k_scan1<<<SB, 1024>>>(N);
    k_scan2<<<1, 1>>>(SB);
    k_scan3<<<NB, 256>>>(N, E);
    k_scatter<<<EB, 256>>>(ei, et, E);

    // ---- layer 0 ----
    k_prep<<<(128 * 64 + 255) / 256, 256>>>(W0, as0, ad0, 128, 4, 64, 256);
    k_gemm<<<dim3(MB, 1), 256, GEMM_SMEM>>>(x, wsd, sd, N, 128, 64, 64, 0);
    k_gemm<<<dim3(MB, 32), 256, GEMM_SMEM>>>(x, W0, xw, N, 128, 256, 2048, 256);
    k_agg<8, true><<<(N * 32 + 255) / 256, 256>>>(xw, sd, ar0, bi0, g0, be0, h, N, 2048, 256);

    // ---- layer 1 ----
    k_prep<<<(256 * 64 + 255) / 256, 256>>>(W1, as1, ad1, 256, 4, 64, 256);
    k_gemm<<<dim3(MB, 1), 256, GEMM_SMEM>>>(h, wsd, sd, N, 256, 64, 64, 0);
    k_gemm<<<dim3(MB, 32), 256, GEMM_SMEM>>>(h, W1, xw, N, 256, 256, 2048, 256);
    k_agg<8, true><<<(N * 32 + 255) / 256, 256>>>(xw, sd, ar1, bi1, g1, be1, h, N, 2048, 256);

    // ---- layer 2 ----
    k_prep<<<(256 * 64 + 255) / 256, 256>>>(W2, as2, ad2, 256, 1, 64, 64);
    k_gemm<<<dim3(MB, 1), 256, GEMM_SMEM>>>(h, wsd, sd, N, 256, 64, 64, 0);
    k_gemm<<<dim3(MB, 8), 256, GEMM_SMEM>>>(h, W2, xw, N, 256, 64, 512, 64);
    k_agg<2, false><<<(N * 32 + 255) / 256, 256>>>(xw, sd, ar2, bi2, nullptr, nullptr, out, N, 512, 64);
}

// round 6
// speedup vs baseline: 1.3393x; 1.3393x over previous
#include <cuda_runtime.h>
#include <cuda_bf16.h>
#include <cstdint>
#include <cstddef>

// RGAT 3-layer on GB300. Per layer:
//  split: x -> (hi,lo) bf16 pair arrays; W -> transposed (n-major) bf16 pairs
//  prep:  fold a_src/a_dst into weights -> wsdT [64][K] bf16 pairs
//  gemm:  sd = X @ wsd ; xw = X @ W[r]   [3xBF16 m16n8k16 mma, cp.async 2-stage]
//  agg :  CSR(warp-per-dst) softmax + gather-sum, fused bias(+LN+ELU)
// 3xBF16: x = hi + lo; hi*hi + hi*lo + lo*hi drops only ~2^-17 lo*lo term.

__device__ float g_xw[102400000];   // 50000*2048
__device__ float g_h [12800000];    // 50000*256
__device__ float g_sd[3200000];     // 50000*64
__device__ __nv_bfloat16 g_ahi[12800000];   // 50000*256
__device__ __nv_bfloat16 g_alo[12800000];
__device__ __nv_bfloat16 g_wthi[524288];    // 8*256*256 (transposed, n-major)
__device__ __nv_bfloat16 g_wtlo[524288];
__device__ __nv_bfloat16 g_wsdthi[16384];   // 64*256
__device__ __nv_bfloat16 g_wsdtlo[16384];
__device__ int   g_cnt[50000];
__device__ int   g_rowptr[50001];
__device__ int   g_cur[50000];
__device__ int   g_psrc[800000];
__device__ int   g_pet [800000];
__device__ int   g_blk[64];
__device__ int   g_is64;

__device__ __forceinline__ void mma_bf16(float c[4], const uint32_t a[4],
                                         uint32_t b0, uint32_t b1) {
    asm volatile(
        "mma.sync.aligned.m16n8k16.row.col.f32.bf16.bf16.f32 "
        "{%0,%1,%2,%3},{%4,%5,%6,%7},{%8,%9},{%0,%1,%2,%3};"
        : "+f"(c[0]), "+f"(c[1]), "+f"(c[2]), "+f"(c[3])
        : "r"(a[0]), "r"(a[1]), "r"(a[2]), "r"(a[3]), "r"(b0), "r"(b1));
}
__device__ __forceinline__ int ld_idx(const void* p, long long i, int is64) {
    return is64 ? (int)((const long long*)p)[i] : ((const int*)p)[i];
}

// ---------------- dtype detect + CSR build ----------------
__global__ void k_detect(const int* ei) {
    if (threadIdx.x == 0 && blockIdx.x == 0) {
        int z = 0;
        for (int i = 1; i < 64; i += 2) z += (ei[i] == 0);
        g_is64 = (z == 32);
    }
}
__global__ void k_zero(int N) {
    int i = blockIdx.x * blockDim.x + threadIdx.x;
    if (i < N) g_cnt[i] = 0;
}
__global__ void k_hist(const void* ei, int E) {
    int e = blockIdx.x * blockDim.x + threadIdx.x;
    if (e < E) atomicAdd(&g_cnt[ld_idx(ei, (long long)E + e, g_is64)], 1);
}
__global__ void k_scan1(int N) {
    __shared__ int sh[1024];
    int t = threadIdx.x, i = blockIdx.x * 1024 + t;
    int v = (i < N) ? g_cnt[i] : 0;
    int x = v; sh[t] = x; __syncthreads();
    for (int off = 1; off < 1024; off <<= 1) {
        int add = (t >= off) ? sh[t - off] : 0;
        __syncthreads();
        x += add; sh[t] = x;
        __syncthreads();
    }
    if (i < N) g_rowptr[i] = x - v;
    if (t == 1023) g_blk[blockIdx.x] = x;
}
__global__ void k_scan2(int nb) {
    if (threadIdx.x == 0 && blockIdx.x == 0) {
        int acc = 0;
        for (int b = 0; b < nb; ++b) { int t = g_blk[b]; g_blk[b] = acc; acc += t; }
    }
}
__global__ void k_scan3(int N, int E) {
    int i = blockIdx.x * blockDim.x + threadIdx.x;
    if (i < N) {
        int v = g_rowptr[i] + g_blk[i >> 10];
        g_rowptr[i] = v; g_cur[i] = v;
    }
    if (i == 0) g_rowptr[N] = E;
}
__global__ void k_scatter(const void* ei, const void* et, int E) {
    int e = blockIdx.x * blockDim.x + threadIdx.x;
    if (e >= E) return;
    int is64 = g_is64;
    int s = ld_idx(ei, e, is64);
    int d = ld_idx(ei, (long long)E + e, is64);
    int t = ld_idx(et, e, is64);
    int pos = atomicAdd(&g_cur[d], 1);
    g_psrc[pos] = s; g_pet[pos] = t;
}

// ---------------- hi/lo splits ----------------
__global__ void k_split(const float* __restrict__ a, __nv_bfloat16* __restrict__ hi,
                        __nv_bfloat16* __restrict__ lo, int n) {
    int i = blockIdx.x * blockDim.x + threadIdx.x;
    if (i >= n) return;
    float x = a[i];
    __nv_bfloat16 h = __float2bfloat16(x);
    hi[i] = h;
    lo[i] = __float2bfloat16(x - __bfloat162float(h));
}
// W[r][k][n] -> WT[(r*Ntot+n)*K + k] as hi/lo bf16
__global__ void k_splitW(const float* __restrict__ W, __nv_bfloat16* __restrict__ hi,
                         __nv_bfloat16* __restrict__ lo, int K, int Ntot, int total) {
    int i = blockIdx.x * blockDim.x + threadIdx.x;
    if (i >= total) return;
    int k = i % K;
    int rn = i / K;
    int n = rn % Ntot;
    int r = rn / Ntot;
    float x = W[((size_t)r * K + k) * Ntot + n];
    __nv_bfloat16 h = __float2bfloat16(x);
    hi[i] = h;
    lo[i] = __float2bfloat16(x - __bfloat162float(h));
}

// ---------------- fold attention vectors ----------------
// wsdT[col][k], col = r*8+q: q<4 -> head q src dot, q>=4 -> head q-4 dst dot
__global__ void k_prep(const float* __restrict__ W, const float* __restrict__ as_,
                       const float* __restrict__ ad_, int K, int H, int C, int Wn) {
    int t = blockIdx.x * blockDim.x + threadIdx.x;
    if (t >= K * 64) return;
    int col = t & 63, k = t >> 6;
    int r = col >> 3, q = col & 7, h = q & 3;
    float acc = 0.f;
    if (h < H) {
        const float* av = ((q & 4) ? ad_ : as_) + h * C;
        const float* wp = W + ((size_t)r * K + k) * Wn + h * C;
        for (int c = 0; c < C; ++c) acc += wp[c] * av[c];
    }
    __nv_bfloat16 hb = __float2bfloat16(acc);
    g_wsdthi[col * K + k] = hb;
    g_wsdtlo[col * K + k] = __float2bfloat16(acc - __bfloat162float(hb));
}

// ---------------- 3xBF16 GEMM, cp.async double-buffered ----------------
// C[row][r*cRel + col] = A[row,:K] @ B[r][:,:64-block]
// smem stage (uint32 words): AsH[128*20] AsL[128*20] BsH[64*20] BsL[64*20]
#define ST_WORDS 7680
#define GEMM_SMEM (size_t)(2 * ST_WORDS * 4)

__device__ __forceinline__ void gemm_load_tile(
    uint32_t* base, int tid, int m0, int M, int K, int kof,
    const __nv_bfloat16* Ahi, const __nv_bfloat16* Alo,
    const __nv_bfloat16* BhiG, const __nv_bfloat16* BloG) {
#pragma unroll
    for (int i = 0; i < 4; ++i) {
        int idx = tid + i * 256;
        int half = idx >> 9, rem = idx & 511;
        int row = rem >> 2, ch = rem & 3;
        int gr = m0 + row;
        const __nv_bfloat16* src = half ? Alo : Ahi;
        const __nv_bfloat16* p = src + (size_t)(gr < M ? gr : 0) * K + kof + ch * 8;
        uint32_t dst = (uint32_t)__cvta_generic_to_shared(base + half * 2560 + row * 20 + ch * 4);
        int sz = (gr < M) ? 16 : 0;
        asm volatile("cp.async.cg.shared.global [%0], [%1], 16, %2;"
                     :: "r"(dst), "l"(p), "r"(sz));
    }
#pragma unroll
    for (int i = 0; i < 2; ++i) {
        int idx = tid + i * 256;
        int half = idx >> 8, rem = idx & 255;
        int col = rem >> 2, ch = rem & 3;
        const __nv_bfloat16* p = (half ? BloG : BhiG) + (size_t)col * K + kof + ch * 8;
        uint32_t dst = (uint32_t)__cvta_generic_to_shared(base + 5120 + half * 1280 + col * 20 + ch * 4);
        asm volatile("cp.async.cg.shared.global [%0], [%1], 16;" :: "r"(dst), "l"(p));
    }
    asm volatile("cp.async.commit_group;");
}

__global__ __launch_bounds__(256, 2) void k_gemm(
    const __nv_bfloat16* __restrict__ Ahi, const __nv_bfloat16* __restrict__ Alo,
    const __nv_bfloat16* __restrict__ Bhi, const __nv_bfloat16* __restrict__ Blo,
    float* __restrict__ C, int M, int K, int Ntot, int crs, int cRel) {
    extern __shared__ uint32_t sm[];
    const int tid = threadIdx.x;
    const int m0 = blockIdx.x * 128;
    const int nblks = Ntot >> 6;
    const int r = blockIdx.y / nblks;
    const int n0 = (blockIdx.y % nblks) << 6;
    const __nv_bfloat16* BhiG = Bhi + ((size_t)r * Ntot + n0) * K;
    const __nv_bfloat16* BloG = Blo + ((size_t)r * Ntot + n0) * K;

    const int lane = tid & 31, wid = tid >> 5;
    const int gid = lane >> 2, tig = lane & 3;
    const int m_off = (wid & 3) * 32, n_off = (wid >> 2) * 32;

    float acc[2][4][4];
#pragma unroll
    for (int f = 0; f < 2; ++f)
#pragma unroll
        for (int n = 0; n < 4; ++n)
#pragma unroll
            for (int q = 0; q < 4; ++q) acc[f][n][q] = 0.f;

    const int nkt = K >> 5;
    gemm_load_tile(sm, tid, m0, M, K, 0, Ahi, Alo, BhiG, BloG);

    for (int kt = 0; kt < nkt; ++kt) {
        if (kt + 1 < nkt) {
            gemm_load_tile(sm + ((kt + 1) & 1) * ST_WORDS, tid, m0, M, K,
                           (kt + 1) * 32, Ahi, Alo, BhiG, BloG);
            asm volatile("cp.async.wait_group 1;");
        } else {
            asm volatile("cp.async.wait_group 0;");
        }
        __syncthreads();
        const uint32_t* base = sm + (kt & 1) * ST_WORDS;
        const uint32_t* AsH = base;
        const uint32_t* AsL = base + 2560;
        const uint32_t* BsH = base + 5120;
        const uint32_t* BsL = base + 6400;
#pragma unroll
        for (int ks = 0; ks < 2; ++ks) {
            uint32_t aH[2][4], aL[2][4];
#pragma unroll
            for (int f = 0; f < 2; ++f) {
                int ro = (m_off + f * 16 + gid) * 20 + ks * 8 + tig;
                aH[f][0] = AsH[ro];           aH[f][1] = AsH[ro + 160];
                aH[f][2] = AsH[ro + 4];       aH[f][3] = AsH[ro + 164];
                aL[f][0] = AsL[ro];           aL[f][1] = AsL[ro + 160];
                aL[f][2] = AsL[ro + 4];       aL[f][3] = AsL[ro + 164];
            }
#pragma unroll
            for (int nf = 0; nf < 4; ++nf) {
                int bo = (n_off + nf * 8 + gid) * 20 + ks * 8 + tig;
                uint32_t bh0 = BsH[bo], bh1 = BsH[bo + 4];
                uint32_t bl0 = BsL[bo], bl1 = BsL[bo + 4];
                mma_bf16(acc[0][nf], aH[0], bh0, bh1);
                mma_bf16(acc[1][nf], aH[1], bh0, bh1);
                mma_bf16(acc[0][nf], aH[0], bl0, bl1);
                mma_bf16(acc[1][nf], aH[1], bl0, bl1);
                mma_bf16(acc[0][nf], aL[0], bh0, bh1);
                mma_bf16(acc[1][nf], aL[1], bh0, bh1);
            }
        }
        __syncthreads();
    }
#pragma unroll
    for (int f = 0; f < 2; ++f) {
        int row = m0 + m_off + f * 16 + gid;
#pragma unroll
        for (int nf = 0; nf < 4; ++nf) {
            int col = n0 + n_off + nf * 8 + 2 * tig;
            if (row < M)
                *(float2*)(C + (size_t)row * crs + (size_t)r * cRel + col) =
                    make_float2(acc[f][nf][0], acc[f][nf][1]);
            if (row + 8 < M)
                *(float2*)(C + (size_t)(row + 8) * crs + (size_t)r * cRel + col) =
                    make_float2(acc[f][nf][2], acc[f][nf][3]);
        }
    }
}

// ---------------- aggregation ----------------
template <int H>
__device__ __forceinline__ void get_alpha(const float* __restrict__ sd,
                                          const float* __restrict__ ar,
                                          int dst, int s, int t, float* a) {
    if (H == 4) {
        float4 sv = *(const float4*)(sd + (size_t)s * 64 + t * 8);
        float4 dv = *(const float4*)(sd + (size_t)dst * 64 + t * 8 + 4);
        float4 av = *(const float4*)(ar + t * 4);
        a[0] = sv.x + dv.x + av.x; a[1] = sv.y + dv.y + av.y;
        a[2] = sv.z + dv.z + av.z; a[3] = sv.w + dv.w + av.w;
    } else {
        a[0] = sd[(size_t)s * 64 + t * 8] + sd[(size_t)dst * 64 + t * 8 + 4] + ar[t];
    }
#pragma unroll
    for (int h = 0; h < H; ++h) a[h] = a[h] > 0.f ? a[h] : 0.2f * a[h];
}

template <int CPL, bool LN>
__global__ __launch_bounds__(256) void k_agg(
    const float* __restrict__ xw, const float* __restrict__ sd,
    const float* __restrict__ ar, const float* __restrict__ bias,
    const float* __restrict__ gamma, const float* __restrict__ beta,
    float* __restrict__ out, int N, int xws, int rls) {
    constexpr int H = CPL * 32 / 64;     // 8->4, 2->1
    constexpr int OUT = CPL * 32;        // 256 or 64
    __shared__ float walpha[8][32][4];
    int w = (blockIdx.x * blockDim.x + threadIdx.x) >> 5;
    if (w >= N) return;
    int lane = threadIdx.x & 31, wl = threadIdx.x >> 5;
    int hh = (lane * CPL) >> 6;
    int beg = g_rowptr[w], end = g_rowptr[w + 1];

    float mx[H];
#pragma unroll
    for (int h = 0; h < H; ++h) mx[h] = -1e30f;
    for (int e = beg + lane; e < end; e += 32) {
        float a[H];
        get_alpha<H>(sd, ar, w, g_psrc[e], g_pet[e], a);
#pragma unroll
        for (int h = 0; h < H; ++h) mx[h] = fmaxf(mx[h], a[h]);
    }
#pragma unroll
    for (int h = 0; h < H; ++h)
#pragma unroll
        for (int o = 16; o; o >>= 1)
            mx[h] = fmaxf(mx[h], __shfl_xor_sync(0xffffffffu, mx[h], o));

    float sm[H];
#pragma unroll
    for (int h = 0; h < H; ++h) sm[h] = 0.f;
    for (int e = beg + lane; e < end; e += 32) {
        float a[H];
        get_alpha<H>(sd, ar, w, g_psrc[e], g_pet[e], a);
#pragma unroll
        for (int h = 0; h < H; ++h) sm[h] += __expf(a[h] - mx[h]);
    }
#pragma unroll
    for (int h = 0; h < H; ++h) {
#pragma unroll
        for (int o = 16; o; o >>= 1) sm[h] += __shfl_xor_sync(0xffffffffu, sm[h], o);
        sm[h] = 1.f / sm[h];
    }

    float acc[CPL];
#pragma unroll
    for (int c = 0; c < CPL; ++c) acc[c] = 0.f;

    for (int base = beg; base < end; base += 32) {
        int e = base + lane;
        int cnt = min(32, end - base);
        int sR = 0, tR = 0;
        if (e < end) {
            sR = g_psrc[e]; tR = g_pet[e];
            float a[H];
            get_alpha<H>(sd, ar, w, sR, tR, a);
#pragma unroll
            for (int h = 0; h < H; ++h)
                walpha[wl][lane][h] = __expf(a[h] - mx[h]) * sm[h];
        }
        __syncwarp();
        for (int j = 0; j < cnt; ++j) {
            int s = __shfl_sync(0xffffffffu, sR, j);
            int t = __shfl_sync(0xffffffffu, tR, j);
            float wv = walpha[wl][j][hh];
            const float* p = xw + (size_t)s * xws + t * rls + lane * CPL;
            if (CPL == 8) {
                float4 v0 = *(const float4*)p, v1 = *(const float4*)(p + 4);
                acc[0] += wv * v0.x; acc[1] += wv * v0.y;
                acc[2] += wv * v0.z; acc[3] += wv * v0.w;
                acc[4] += wv * v1.x; acc[5] += wv * v1.y;
                acc[6] += wv * v1.z; acc[7] += wv * v1.w;
            } else {
                float2 v = *(const float2*)p;
                acc[0] += wv * v.x; acc[1] += wv * v.y;
            }
        }
        __syncwarp();
    }

    if (LN) {
        float4 b0 = *(const float4*)(bias + lane * 8);
        float4 b1 = *(const float4*)(bias + lane * 8 + 4);
        acc[0] += b0.x; acc[1] += b0.y; acc[2] += b0.z; acc[3] += b0.w;
        acc[4] += b1.x; acc[5] += b1.y; acc[6] += b1.z; acc[7] += b1.w;
        float s1 = 0.f;
#pragma unroll
        for (int c = 0; c < CPL; ++c) s1 += acc[c];
#pragma unroll
        for (int o = 16; o; o >>= 1) s1 += __shfl_xor_sync(0xffffffffu, s1, o);
        float m = s1 / (float)OUT;
        float s2 = 0.f;
#pragma unroll
        for (int c = 0; c < CPL; ++c) { float d = acc[c] - m; s2 += d * d; }
#pragma unroll
        for (int o = 16; o; o >>= 1) s2 += __shfl_xor_sync(0xffffffffu, s2, o);
        float rstd = rsqrtf(s2 / (float)OUT + 1e-5f);
        float4 gA = *(const float4*)(gamma + lane * 8);
        float4 gB = *(const float4*)(gamma + lane * 8 + 4);
        float4 tA = *(const float4*)(beta + lane * 8);
        float4 tB = *(const float4*)(beta + lane * 8 + 4);
        float gm[8] = {gA.x, gA.y, gA.z, gA.w, gB.x, gB.y, gB.z, gB.w};
        float bt[8] = {tA.x, tA.y, tA.z, tA.w, tB.x, tB.y, tB.z, tB.w};
        float4 o0, o1;
#pragma unroll
        for (int c = 0; c < 8; ++c) {
            float y = gm[c] * (acc[c] - m) * rstd + bt[c];
            y = y > 0.f ? y : (expf(y) - 1.f);
            if (c < 4) (&o0.x)[c] = y; else (&o1.x)[c - 4] = y;
        }
        *(float4*)(out + (size_t)w * OUT + lane * 8) = o0;
        *(float4*)(out + (size_t)w * OUT + lane * 8 + 4) = o1;
    } else {
        out[(size_t)w * OUT + lane * 2] = acc[0] + bias[lane * 2];
        out[(size_t)w * OUT + lane * 2 + 1] = acc[1] + bias[lane * 2 + 1];
    }
}

// ---------------- launch ----------------
extern "C" void kernel_launch(void* const* d_in, const int* in_sizes, int n_in,
                              void* d_out, int out_size) {
    const float* x   = (const float*)d_in[0];
    const void*  ei  = d_in[1];
    const void*  et  = d_in[2];
    const float* W0  = (const float*)d_in[3];
    const float* as0 = (const float*)d_in[4];
    const float* ad0 = (const float*)d_in[5];
    const float* ar0 = (const float*)d_in[6];
    const float* bi0 = (const float*)d_in[7];
    const float* W1  = (const float*)d_in[8];
    const float* as1 = (const float*)d_in[9];
    const float* ad1 = (const float*)d_in[10];
    const float* ar1 = (const float*)d_in[11];
    const float* bi1 = (const float*)d_in[12];
    const float* W2  = (const float*)d_in[13];
    const float* as2 = (const float*)d_in[14];
    const float* ad2 = (const float*)d_in[15];
    const float* ar2 = (const float*)d_in[16];
    const float* bi2 = (const float*)d_in[17];
    const float* g0  = (const float*)d_in[18];
    const float* be0 = (const float*)d_in[19];
    const float* g1  = (const float*)d_in[20];
    const float* be1 = (const float*)d_in[21];

    const int N = in_sizes[0] / 128;        // 50000
    const int E = in_sizes[2];              // 800000
    float* out = (float*)d_out;

    float *xw, *h, *sd;
    __nv_bfloat16 *ahi, *alo, *wthi, *wtlo, *wsdthi, *wsdtlo;
    cudaGetSymbolAddress((void**)&xw, g_xw);
    cudaGetSymbolAddress((void**)&h, g_h);
    cudaGetSymbolAddress((void**)&sd, g_sd);
    cudaGetSymbolAddress((void**)&ahi, g_ahi);
    cudaGetSymbolAddress((void**)&alo, g_alo);
    cudaGetSymbolAddress((void**)&wthi, g_wthi);
    cudaGetSymbolAddress((void**)&wtlo, g_wtlo);
    cudaGetSymbolAddress((void**)&wsdthi, g_wsdthi);
    cudaGetSymbolAddress((void**)&wsdtlo, g_wsdtlo);

    static int smem_set = 0;
    if (!smem_set) {
        cudaFuncSetAttribute(k_gemm, cudaFuncAttributeMaxDynamicSharedMemorySize,
                             (int)GEMM_SMEM);
        smem_set = 1;
    }

    const int MB = (N + 127) / 128;         // 391
    const int EB = (E + 255) / 256;
    const int NB = (N + 255) / 256;
    const int SB = (N + 1023) / 1024;

    // CSR build
    k_detect<<<1, 32>>>((const int*)ei);
    k_zero<<<NB, 256>>>(N);
    k_hist<<<EB, 256>>>(ei, E);
    k_scan1<<<SB, 1024>>>(N);
    k_scan2<<<1, 1>>>(SB);
    k_scan3<<<NB, 256>>>(N, E);
    k_scatter<<<EB, 256>>>(ei, et, E);

    // ---- layer 0 (K=128) ----
    k_split<<<(N * 128 + 255) / 256, 256>>>(x, ahi, alo, N * 128);
    k_prep<<<(128 * 64 + 255) / 256, 256>>>(W0, as0, ad0, 128, 4, 64, 256);
    k_splitW<<<(8 * 128 * 256 + 255) / 256, 256>>>(W0, wthi, wtlo, 128, 256, 8 * 128 * 256);
    k_gemm<<<dim3(MB, 1), 256, GEMM_SMEM>>>(ahi, alo, wsdthi, wsdtlo, sd, N, 128, 64, 64, 0);
    k_gemm<<<dim3(MB, 32), 256, GEMM_SMEM>>>(ahi, alo, wthi, wtlo, xw, N, 128, 256, 2048, 256);
    k_agg<8, true><<<(N * 32 + 255) / 256, 256>>>(xw, sd, ar0, bi0, g0, be0, h, N, 2048, 256);

    // ---- layer 1 (K=256) ----
    k_split<<<(N * 256 + 255) / 256, 256>>>(h, ahi, alo, N * 256);
    k_prep<<<(256 * 64 + 255) / 256, 256>>>(W1, as1, ad1, 256, 4, 64, 256);
    k_splitW<<<(8 * 256 * 256 + 255) / 256, 256>>>(W1, wthi, wtlo, 256, 256, 8 * 256 * 256);
    k_gemm<<<dim3(MB, 1), 256, GEMM_SMEM>>>(ahi, alo, wsdthi, wsdtlo, sd, N, 256, 64, 64, 0);
    k_gemm<<<dim3(MB, 32), 256, GEMM_SMEM>>>(ahi, alo, wthi, wtlo, xw, N, 256, 256, 2048, 256);
    k_agg<8, true><<<(N * 32 + 255) / 256, 256>>>(xw, sd, ar1, bi1, g1, be1, h, N, 2048, 256);

    // ---- layer 2 (K=256, out 64, mean over 1 head) ----
    k_split<<<(N * 256 + 255) / 256, 256>>>(h, ahi, alo, N * 256);
    k_prep<<<(256 * 64 + 255) / 256, 256>>>(W2, as2, ad2, 256, 1, 64, 64);
    k_splitW<<<(8 * 256 * 64 + 255) / 256, 256>>>(W2, wthi, wtlo, 256, 64, 8 * 256 * 64);
    k_gemm<<<dim3(MB, 1), 256, GEMM_SMEM>>>(ahi, alo, wsdthi, wsdtlo, sd, N, 256, 64, 64, 0);
    k_gemm<<<dim3(MB, 8), 256, GEMM_SMEM>>>(ahi, alo, wthi, wtlo, xw, N, 256, 64, 512, 64);
    k_agg<2, false><<<(N * 32 + 255) / 256, 256>>>(xw, sd, ar2, bi2, nullptr, nullptr, out, N, 512, 64);
}

// round 11
// speedup vs baseline: 1.3952x; 1.0418x over previous
#include <cuda_runtime.h>
#include <cuda_bf16.h>
#include <cstdint>
#include <cstddef>

// RGAT 3-layer on GB300 (legacy mma.sync path — tcgen05 not supported by the
// harness toolchain: PTX .target sm_103 lacks the 'a' feature set).
//  split: x -> (hi,lo) bf16 arrays; W -> transposed (n-major) bf16 pairs
//  gemm:  sd = X @ wsd ; xw = X @ W[r]   [3xBF16 m16n8k16 mma, cp.async 2-stage]
//  agg :  CSR(warp-per-dst) ONLINE softmax + gather-sum, fused bias+LN+ELU,
//         epilogue emits next layer's (hi,lo) bf16 directly (no split kernel).

__device__ float g_xw[102400000];           // 50000*2048
__device__ float g_sd[3200000];             // 50000*64
__device__ __nv_bfloat16 g_ahi[12800000];   // 50000*256
__device__ __nv_bfloat16 g_alo[12800000];
__device__ __nv_bfloat16 g_wthi[524288];    // 8*256*256 (transposed, n-major)
__device__ __nv_bfloat16 g_wtlo[524288];
__device__ __nv_bfloat16 g_wsdthi[16384];   // 64*256
__device__ __nv_bfloat16 g_wsdtlo[16384];
__device__ int   g_cnt[50000];
__device__ int   g_rowptr[50001];
__device__ int   g_cur[50000];
__device__ int2  g_pse[800000];             // (src, etype) packed
__device__ int   g_blk[64];
__device__ int   g_is64;

__device__ __forceinline__ void mma_bf16(float c[4], const uint32_t a[4],
                                         uint32_t b0, uint32_t b1) {
    asm volatile(
        "mma.sync.aligned.m16n8k16.row.col.f32.bf16.bf16.f32 "
        "{%0,%1,%2,%3},{%4,%5,%6,%7},{%8,%9},{%0,%1,%2,%3};"
        : "+f"(c[0]), "+f"(c[1]), "+f"(c[2]), "+f"(c[3])
        : "r"(a[0]), "r"(a[1]), "r"(a[2]), "r"(a[3]), "r"(b0), "r"(b1));
}
__device__ __forceinline__ int ld_idx(const void* p, long long i, int is64) {
    return is64 ? (int)((const long long*)p)[i] : ((const int*)p)[i];
}

// ---------------- dtype detect + CSR build ----------------
__global__ void k_detect(const int* ei) {
    if (threadIdx.x == 0 && blockIdx.x == 0) {
        int z = 0;
        for (int i = 1; i < 64; i += 2) z += (ei[i] == 0);
        g_is64 = (z == 32);
    }
}
__global__ void k_zero(int N) {
    int i = blockIdx.x * blockDim.x + threadIdx.x;
    if (i < N) g_cnt[i] = 0;
}
__global__ void k_hist(const void* ei, int E) {
    int e = blockIdx.x * blockDim.x + threadIdx.x;
    if (e < E) atomicAdd(&g_cnt[ld_idx(ei, (long long)E + e, g_is64)], 1);
}
__global__ void k_scan1(int N) {
    __shared__ int sh[1024];
    int t = threadIdx.x, i = blockIdx.x * 1024 + t;
    int v = (i < N) ? g_cnt[i] : 0;
    int x = v; sh[t] = x; __syncthreads();
    for (int off = 1; off < 1024; off <<= 1) {
        int add = (t >= off) ? sh[t - off] : 0;
        __syncthreads();
        x += add; sh[t] = x;
        __syncthreads();
    }
    if (i < N) g_rowptr[i] = x - v;
    if (t == 1023) g_blk[blockIdx.x] = x;
}
__global__ void k_scan2(int nb) {
    if (threadIdx.x == 0 && blockIdx.x == 0) {
        int acc = 0;
        for (int b = 0; b < nb; ++b) { int t = g_blk[b]; g_blk[b] = acc; acc += t; }
    }
}
__global__ void k_scan3(int N, int E) {
    int i = blockIdx.x * blockDim.x + threadIdx.x;
    if (i < N) {
        int v = g_rowptr[i] + g_blk[i >> 10];
        g_rowptr[i] = v; g_cur[i] = v;
    }
    if (i == 0) g_rowptr[N] = E;
}
__global__ void k_scatter(const void* ei, const void* et, int E) {
    int e = blockIdx.x * blockDim.x + threadIdx.x;
    if (e >= E) return;
    int is64 = g_is64;
    int s = ld_idx(ei, e, is64);
    int d = ld_idx(ei, (long long)E + e, is64);
    int t = ld_idx(et, e, is64);
    int pos = atomicAdd(&g_cur[d], 1);
    g_pse[pos] = make_int2(s, t);
}

// ---------------- hi/lo splits (layer-0 input only) ----------------
__global__ void k_split(const float* __restrict__ a, __nv_bfloat16* __restrict__ hi,
                        __nv_bfloat16* __restrict__ lo, int n) {
    int i = blockIdx.x * blockDim.x + threadIdx.x;
    if (i >= n) return;
    float x = a[i];
    __nv_bfloat16 h = __float2bfloat16(x);
    hi[i] = h;
    lo[i] = __float2bfloat16(x - __bfloat162float(h));
}
// W[r][k][n] -> WT[(r*Ntot+n)*K + k] as hi/lo bf16
__global__ void k_splitW(const float* __restrict__ W, __nv_bfloat16* __restrict__ hi,
                         __nv_bfloat16* __restrict__ lo, int K, int Ntot, int total) {
    int i = blockIdx.x * blockDim.x + threadIdx.x;
    if (i >= total) return;
    int k = i % K;
    int rn = i / K;
    int n = rn % Ntot;
    int r = rn / Ntot;
    float x = W[((size_t)r * K + k) * Ntot + n];
    __nv_bfloat16 h = __float2bfloat16(x);
    hi[i] = h;
    lo[i] = __float2bfloat16(x - __bfloat162float(h));
}

// ---------------- fold attention vectors ----------------
// wsdT[col][k], col = r*8+q: q<4 -> head q src dot, q>=4 -> head q-4 dst dot
__global__ void k_prep(const float* __restrict__ W, const float* __restrict__ as_,
                       const float* __restrict__ ad_, int K, int H, int C, int Wn) {
    int t = blockIdx.x * blockDim.x + threadIdx.x;
    if (t >= K * 64) return;
    int col = t & 63, k = t >> 6;
    int r = col >> 3, q = col & 7, h = q & 3;
    float acc = 0.f;
    if (h < H) {
        const float* av = ((q & 4) ? ad_ : as_) + h * C;
        const float* wp = W + ((size_t)r * K + k) * Wn + h * C;
        for (int c = 0; c < C; ++c) acc += wp[c] * av[c];
    }
    __nv_bfloat16 hb = __float2bfloat16(acc);
    g_wsdthi[col * K + k] = hb;
    g_wsdtlo[col * K + k] = __float2bfloat16(acc - __bfloat162float(hb));
}

// ---------------- 3xBF16 GEMM, cp.async double-buffered ----------------
// C[row][r*cRel + col] = A[row,:K] @ B[r][:,:64-block]
// smem stage (uint32 words): AsH[128*20] AsL[128*20] BsH[64*20] BsL[64*20]
#define ST_WORDS 7680
#define GEMM_SMEM (size_t)(2 * ST_WORDS * 4)

__device__ __forceinline__ void gemm_load_tile(
    uint32_t* base, int tid, int m0, int M, int K, int kof,
    const __nv_bfloat16* Ahi, const __nv_bfloat16* Alo,
    const __nv_bfloat16* BhiG, const __nv_bfloat16* BloG) {
#pragma unroll
    for (int i = 0; i < 4; ++i) {
        int idx = tid + i * 256;
        int half = idx >> 9, rem = idx & 511;
        int row = rem >> 2, ch = rem & 3;
        int gr = m0 + row;
        const __nv_bfloat16* src = half ? Alo : Ahi;
        const __nv_bfloat16* p = src + (size_t)(gr < M ? gr : 0) * K + kof + ch * 8;
        uint32_t dst = (uint32_t)__cvta_generic_to_shared(base + half * 2560 + row * 20 + ch * 4);
        int sz = (gr < M) ? 16 : 0;
        asm volatile("cp.async.cg.shared.global [%0], [%1], 16, %2;"
                     :: "r"(dst), "l"(p), "r"(sz));
    }
#pragma unroll
    for (int i = 0; i < 2; ++i) {
        int idx = tid + i * 256;
        int half = idx >> 8, rem = idx & 255;
        int col = rem >> 2, ch = rem & 3;
        const __nv_bfloat16* p = (half ? BloG : BhiG) + (size_t)col * K + kof + ch * 8;
        uint32_t dst = (uint32_t)__cvta_generic_to_shared(base + 5120 + half * 1280 + col * 20 + ch * 4);
        asm volatile("cp.async.cg.shared.global [%0], [%1], 16;" :: "r"(dst), "l"(p));
    }
    asm volatile("cp.async.commit_group;");
}

__global__ __launch_bounds__(256, 2) void k_gemm(
    const __nv_bfloat16* __restrict__ Ahi, const __nv_bfloat16* __restrict__ Alo,
    const __nv_bfloat16* __restrict__ Bhi, const __nv_bfloat16* __restrict__ Blo,
    float* __restrict__ C, int M, int K, int Ntot, int crs, int cRel) {
    extern __shared__ uint32_t sm[];
    const int tid = threadIdx.x;
    const int m0 = blockIdx.x * 128;
    const int nblks = Ntot >> 6;
    const int r = blockIdx.y / nblks;
    const int n0 = (blockIdx.y % nblks) << 6;
    const __nv_bfloat16* BhiG = Bhi + ((size_t)r * Ntot + n0) * K;
    const __nv_bfloat16* BloG = Blo + ((size_t)r * Ntot + n0) * K;

    const int lane = tid & 31, wid = tid >> 5;
    const int gid = lane >> 2, tig = lane & 3;
    const int m_off = (wid & 3) * 32, n_off = (wid >> 2) * 32;

    float acc[2][4][4];
#pragma unroll
    for (int f = 0; f < 2; ++f)
#pragma unroll
        for (int n = 0; n < 4; ++n)
#pragma unroll
            for (int q = 0; q < 4; ++q) acc[f][n][q] = 0.f;

    const int nkt = K >> 5;
    gemm_load_tile(sm, tid, m0, M, K, 0, Ahi, Alo, BhiG, BloG);

    for (int kt = 0; kt < nkt; ++kt) {
        if (kt + 1 < nkt) {
            gemm_load_tile(sm + ((kt + 1) & 1) * ST_WORDS, tid, m0, M, K,
                           (kt + 1) * 32, Ahi, Alo, BhiG, BloG);
            asm volatile("cp.async.wait_group 1;");
        } else {
            asm volatile("cp.async.wait_group 0;");
        }
        __syncthreads();
        const uint32_t* base = sm + (kt & 1) * ST_WORDS;
        const uint32_t* AsH = base;
        const uint32_t* AsL = base + 2560;
        const uint32_t* BsH = base + 5120;
        const uint32_t* BsL = base + 6400;
#pragma unroll
        for (int ks = 0; ks < 2; ++ks) {
            uint32_t aH[2][4], aL[2][4];
#pragma unroll
            for (int f = 0; f < 2; ++f) {
                int ro = (m_off + f * 16 + gid) * 20 + ks * 8 + tig;
                aH[f][0] = AsH[ro];           aH[f][1] = AsH[ro + 160];
                aH[f][2] = AsH[ro + 4];       aH[f][3] = AsH[ro + 164];
                aL[f][0] = AsL[ro];           aL[f][1] = AsL[ro + 160];
                aL[f][2] = AsL[ro + 4];       aL[f][3] = AsL[ro + 164];
            }
#pragma unroll
            for (int nf = 0; nf < 4; ++nf) {
                int bo = (n_off + nf * 8 + gid) * 20 + ks * 8 + tig;
                uint32_t bh0 = BsH[bo], bh1 = BsH[bo + 4];
                uint32_t bl0 = BsL[bo], bl1 = BsL[bo + 4];
                mma_bf16(acc[0][nf], aH[0], bh0, bh1);
                mma_bf16(acc[1][nf], aH[1], bh0, bh1);
                mma_bf16(acc[0][nf], aH[0], bl0, bl1);
                mma_bf16(acc[1][nf], aH[1], bl0, bl1);
                mma_bf16(acc[0][nf], aL[0], bh0, bh1);
                mma_bf16(acc[1][nf], aL[1], bh0, bh1);
            }
        }
        __syncthreads();
    }
#pragma unroll
    for (int f = 0; f < 2; ++f) {
        int row = m0 + m_off + f * 16 + gid;
#pragma unroll
        for (int nf = 0; nf < 4; ++nf) {
            int col = n0 + n_off + nf * 8 + 2 * tig;
            if (row < M)
                *(float2*)(C + (size_t)row * crs + (size_t)r * cRel + col) =
                    make_float2(acc[f][nf][0], acc[f][nf][1]);
            if (row + 8 < M)
                *(float2*)(C + (size_t)(row + 8) * crs + (size_t)r * cRel + col) =
                    make_float2(acc[f][nf][2], acc[f][nf][3]);
        }
    }
}

// ---------------- aggregation (online softmax, fused LN+ELU+split) ----------------
template <int H>
__device__ __forceinline__ void get_alpha(const float* __restrict__ sd,
                                          const float* __restrict__ ar,
                                          int dst, int s, int t, float* a) {
    if (H == 4) {
        float4 sv = *(const float4*)(sd + (size_t)s * 64 + t * 8);
        float4 dv = *(const float4*)(sd + (size_t)dst * 64 + t * 8 + 4);
        float4 av = *(const float4*)(ar + t * 4);
        a[0] = sv.x + dv.x + av.x; a[1] = sv.y + dv.y + av.y;
        a[2] = sv.z + dv.z + av.z; a[3] = sv.w + dv.w + av.w;
    } else {
        a[0] = sd[(size_t)s * 64 + t * 8] + sd[(size_t)dst * 64 + t * 8 + 4] + ar[t];
    }
#pragma unroll
    for (int h = 0; h < H; ++h) a[h] = a[h] > 0.f ? a[h] : 0.2f * a[h];
}

template <int CPL, bool LN>
__global__ __launch_bounds__(256) void k_agg(
    const float* __restrict__ xw, const float* __restrict__ sd,
    const float* __restrict__ ar, const float* __restrict__ bias,
    const float* __restrict__ gamma, const float* __restrict__ beta,
    float* __restrict__ out, __nv_bfloat16* __restrict__ ohi,
    __nv_bfloat16* __restrict__ olo, int N, int xws, int rls) {
    constexpr int H = CPL * 32 / 64;     // 8->4, 2->1
    constexpr int OUT = CPL * 32;        // 256 or 64
    __shared__ float walpha[8][32][4];
    int w = (blockIdx.x * blockDim.x + threadIdx.x) >> 5;
    if (w >= N) return;
    int lane = threadIdx.x & 31, wl = threadIdx.x >> 5;
    int hh = (lane * CPL) >> 6;
    int beg = g_rowptr[w], end = g_rowptr[w + 1];

    // online softmax: single edge pass computing (max, scaled-sum)
    float mx[H], dn[H];
#pragma unroll
    for (int h = 0; h < H; ++h) { mx[h] = -1e30f; dn[h] = 0.f; }
    for (int e = beg + lane; e < end; e += 32) {
        int2 pe = g_pse[e];
        float a[H];
        get_alpha<H>(sd, ar, w, pe.x, pe.y, a);
#pragma unroll
        for (int h = 0; h < H; ++h) {
            float mn = fmaxf(mx[h], a[h]);
            dn[h] = dn[h] * __expf(mx[h] - mn) + __expf(a[h] - mn);
            mx[h] = mn;
        }
    }
#pragma unroll
    for (int h = 0; h < H; ++h) {
#pragma unroll
        for (int o = 16; o; o >>= 1) {
            float mo = __shfl_xor_sync(0xffffffffu, mx[h], o);
            float dd = __shfl_xor_sync(0xffffffffu, dn[h], o);
            float mn = fmaxf(mx[h], mo);
            dn[h] = dn[h] * __expf(mx[h] - mn) + dd * __expf(mo - mn);
            mx[h] = mn;
        }
        dn[h] = 1.f / dn[h];
    }

    float acc[CPL];
#pragma unroll
    for (int c = 0; c < CPL; ++c) acc[c] = 0.f;

    for (int base = beg; base < end; base += 32) {
        int e = base + lane;
        int cnt = min(32, end - base);
        int sR = 0, tR = 0;
        if (e < end) {
            int2 pe = g_pse[e];
            sR = pe.x; tR = pe.y;
            float a[H];
            get_alpha<H>(sd, ar, w, sR, tR, a);
#pragma unroll
            for (int h = 0; h < H; ++h)
                walpha[wl][lane][h] = __expf(a[h] - mx[h]) * dn[h];
        }
        __syncwarp();
        for (int j = 0; j < cnt; ++j) {
            int s = __shfl_sync(0xffffffffu, sR, j);
            int t = __shfl_sync(0xffffffffu, tR, j);
            float wv = walpha[wl][j][hh];
            const float* p = xw + (size_t)s * xws + t * rls + lane * CPL;
            if (CPL == 8) {
                float4 v0 = *(const float4*)p, v1 = *(const float4*)(p + 4);
                acc[0] += wv * v0.x; acc[1] += wv * v0.y;
                acc[2] += wv * v0.z; acc[3] += wv * v0.w;
                acc[4] += wv * v1.x; acc[5] += wv * v1.y;
                acc[6] += wv * v1.z; acc[7] += wv * v1.w;
            } else {
                float2 v = *(const float2*)p;
                acc[0] += wv * v.x; acc[1] += wv * v.y;
            }
        }
        __syncwarp();
    }

    if (LN) {
        float4 b0 = *(const float4*)(bias + lane * 8);
        float4 b1 = *(const float4*)(bias + lane * 8 + 4);
        acc[0] += b0.x; acc[1] += b0.y; acc[2] += b0.z; acc[3] += b0.w;
        acc[4] += b1.x; acc[5] += b1.y; acc[6] += b1.z; acc[7] += b1.w;
        float s1 = 0.f;
#pragma unroll
        for (int c = 0; c < CPL; ++c) s1 += acc[c];
#pragma unroll
        for (int o = 16; o; o >>= 1) s1 += __shfl_xor_sync(0xffffffffu, s1, o);
        float m = s1 / (float)OUT;
        float s2 = 0.f;
#pragma unroll
        for (int c = 0; c < CPL; ++c) { float d = acc[c] - m; s2 += d * d; }
#pragma unroll
        for (int o = 16; o; o >>= 1) s2 += __shfl_xor_sync(0xffffffffu, s2, o);
        float rstd = rsqrtf(s2 / (float)OUT + 1e-5f);
        float4 gA = *(const float4*)(gamma + lane * 8);
        float4 gB = *(const float4*)(gamma + lane * 8 + 4);
        float4 tA = *(const float4*)(beta + lane * 8);
        float4 tB = *(const float4*)(beta + lane * 8 + 4);
        float gm[8] = {gA.x, gA.y, gA.z, gA.w, gB.x, gB.y, gB.z, gB.w};
        float bt[8] = {tA.x, tA.y, tA.z, tA.w, tB.x, tB.y, tB.z, tB.w};
        __nv_bfloat16 hv[8], lv[8];
#pragma unroll
        for (int c = 0; c < 8; ++c) {
            float y = gm[c] * (acc[c] - m) * rstd + bt[c];
            y = y > 0.f ? y : (expf(y) - 1.f);
            hv[c] = __float2bfloat16(y);
            lv[c] = __float2bfloat16(y - __bfloat162float(hv[c]));
        }
        *(float4*)(ohi + (size_t)w * OUT + lane * 8) = *(float4*)hv;
        *(float4*)(olo + (size_t)w * OUT + lane * 8) = *(float4*)lv;
    } else {
        out[(size_t)w * OUT + lane * 2] = acc[0] + bias[lane * 2];
        out[(size_t)w * OUT + lane * 2 + 1] = acc[1] + bias[lane * 2 + 1];
    }
}

// ---------------- launch ----------------
extern "C" void kernel_launch(void* const* d_in, const int* in_sizes, int n_in,
                              void* d_out, int out_size) {
    const float* x   = (const float*)d_in[0];
    const void*  ei  = d_in[1];
    const void*  et  = d_in[2];
    const float* W0  = (const float*)d_in[3];
    const float* as0 = (const float*)d_in[4];
    const float* ad0 = (const float*)d_in[5];
    const float* ar0 = (const float*)d_in[6];
    const float* bi0 = (const float*)d_in[7];
    const float* W1  = (const float*)d_in[8];
    const float* as1 = (const float*)d_in[9];
    const float* ad1 = (const float*)d_in[10];
    const float* ar1 = (const float*)d_in[11];
    const float* bi1 = (const float*)d_in[12];
    const float* W2  = (const float*)d_in[13];
    const float* as2 = (const float*)d_in[14];
    const float* ad2 = (const float*)d_in[15];
    const float* ar2 = (const float*)d_in[16];
    const float* bi2 = (const float*)d_in[17];
    const float* g0  = (const float*)d_in[18];
    const float* be0 = (const float*)d_in[19];
    const float* g1  = (const float*)d_in[20];
    const float* be1 = (const float*)d_in[21];

    const int N = in_sizes[0] / 128;        // 50000
    const int E = in_sizes[2];              // 800000
    float* out = (float*)d_out;

    float *xw, *sd;
    __nv_bfloat16 *ahi, *alo, *wthi, *wtlo, *wsdthi, *wsdtlo;
    cudaGetSymbolAddress((void**)&xw, g_xw);
    cudaGetSymbolAddress((void**)&sd, g_sd);
    cudaGetSymbolAddress((void**)&ahi, g_ahi);
    cudaGetSymbolAddress((void**)&alo, g_alo);
    cudaGetSymbolAddress((void**)&wthi, g_wthi);
    cudaGetSymbolAddress((void**)&wtlo, g_wtlo);
    cudaGetSymbolAddress((void**)&wsdthi, g_wsdthi);
    cudaGetSymbolAddress((void**)&wsdtlo, g_wsdtlo);

    static int smem_set = 0;
    if (!smem_set) {
        cudaFuncSetAttribute(k_gemm, cudaFuncAttributeMaxDynamicSharedMemorySize,
                             (int)GEMM_SMEM);
        smem_set = 1;
    }

    const int MB = (N + 127) / 128;         // 391
    const int EB = (E + 255) / 256;
    const int NB = (N + 255) / 256;
    const int SB = (N + 1023) / 1024;

    // ---- layer 0 dense front (big GEMM early in launch order for ncu) ----
    k_split<<<(N * 128 + 255) / 256, 256>>>(x, ahi, alo, N * 128);
    k_splitW<<<(8 * 128 * 256 + 255) / 256, 256>>>(W0, wthi, wtlo, 128, 256, 8 * 128 * 256);
    k_prep<<<(128 * 64 + 255) / 256, 256>>>(W0, as0, ad0, 128, 4, 64, 256);
    k_gemm<<<dim3(MB, 32), 256, GEMM_SMEM>>>(ahi, alo, wthi, wtlo, xw, N, 128, 256, 2048, 256);
    k_gemm<<<dim3(MB, 1), 256, GEMM_SMEM>>>(ahi, alo, wsdthi, wsdtlo, sd, N, 128, 64, 64, 0);

    // ---- CSR build ----
    k_detect<<<1, 32>>>((const int*)ei);
    k_zero<<<NB, 256>>>(N);
    k_hist<<<EB, 256>>>(ei, E);
    k_scan1<<<SB, 1024>>>(N);
    k_scan2<<<1, 1>>>(SB);
    k_scan3<<<NB, 256>>>(N, E);
    k_scatter<<<EB, 256>>>(ei, et, E);

    k_agg<8, true><<<(N * 32 + 255) / 256, 256>>>(xw, sd, ar0, bi0, g0, be0,
                                                  nullptr, ahi, alo, N, 2048, 256);

    // ---- layer 1 (K=256) ----
    k_splitW<<<(8 * 256 * 256 + 255) / 256, 256>>>(W1, wthi, wtlo, 256, 256, 8 * 256 * 256);
    k_prep<<<(256 * 64 + 255) / 256, 256>>>(W1, as1, ad1, 256, 4, 64, 256);
    k_gemm<<<dim3(MB, 1), 256, GEMM_SMEM>>>(ahi, alo, wsdthi, wsdtlo, sd, N, 256, 64, 64, 0);
    k_gemm<<<dim3(MB, 32), 256, GEMM_SMEM>>>(ahi, alo, wthi, wtlo, xw, N, 256, 256, 2048, 256);
    k_agg<8, true><<<(N * 32 + 255) / 256, 256>>>(xw, sd, ar1, bi1, g1, be1,
                                                  nullptr, ahi, alo, N, 2048, 256);

    // ---- layer 2 (K=256, out 64, 1 head) ----
    k_splitW<<<(8 * 256 * 64 + 255) / 256, 256>>>(W2, wthi, wtlo, 256, 64, 8 * 256 * 64);
    k_prep<<<(256 * 64 + 255) / 256, 256>>>(W2, as2, ad2, 256, 1, 64, 64);
    k_gemm<<<dim3(MB, 1), 256, GEMM_SMEM>>>(ahi, alo, wsdthi, wsdtlo, sd, N, 256, 64, 64, 0);
    k_gemm<<<dim3(MB, 8), 256, GEMM_SMEM>>>(ahi, alo, wthi, wtlo, xw, N, 256, 64, 512, 64);
    k_agg<2, false><<<(N * 32 + 255) / 256, 256>>>(xw, sd, ar2, bi2, nullptr, nullptr,
                                                   out, nullptr, nullptr, N, 512, 64);
}

// round 12
// speedup vs baseline: 1.4553x; 1.0431x over previous
#include <cuda_runtime.h>
#include <cuda_bf16.h>
#include <cstdint>
#include <cstddef>

// RGAT 3-layer on GB300 (legacy mma.sync path — tcgen05 unsupported by harness
// toolchain). B (split weights) is ONE global col-major matrix of G columns
// (G = 8*Ntot); C col index r*cRel+n == global col. So the xw GEMM is a plain
// [M,K]x[K,G] GEMM tiled BM=256 x BN=128 (512 thr) to halve L2 tile re-reads.
//  gemm:  3xBF16 m16n8k16 (hi*hi + hi*lo + lo*hi), cp.async double-buffered
//  agg :  CSR(warp-per-dst) online softmax + gather-sum, fused bias+LN+ELU,
//         epilogue emits next layer's (hi,lo) bf16 directly.

__device__ float g_xw[102400000];           // 50000*2048
__device__ float g_sd[3200000];             // 50000*64
__device__ __nv_bfloat16 g_ahi[12800000];   // 50000*256
__device__ __nv_bfloat16 g_alo[12800000];
__device__ __nv_bfloat16 g_wthi[524288];    // 8*256*256 (global col-major)
__device__ __nv_bfloat16 g_wtlo[524288];
__device__ __nv_bfloat16 g_wsdthi[16384];   // 64*256
__device__ __nv_bfloat16 g_wsdtlo[16384];
__device__ int   g_cnt[50000];
__device__ int   g_rowptr[50001];
__device__ int   g_cur[50000];
__device__ int2  g_pse[800000];             // (src, etype)
__device__ int   g_blk[64];
__device__ int   g_is64;

__device__ __forceinline__ void mma_bf16(float c[4], const uint32_t a[4],
                                         uint32_t b0, uint32_t b1) {
    asm volatile(
        "mma.sync.aligned.m16n8k16.row.col.f32.bf16.bf16.f32 "
        "{%0,%1,%2,%3},{%4,%5,%6,%7},{%8,%9},{%0,%1,%2,%3};"
        : "+f"(c[0]), "+f"(c[1]), "+f"(c[2]), "+f"(c[3])
        : "r"(a[0]), "r"(a[1]), "r"(a[2]), "r"(a[3]), "r"(b0), "r"(b1));
}
__device__ __forceinline__ int ld_idx(const void* p, long long i, int is64) {
    return is64 ? (int)((const long long*)p)[i] : ((const int*)p)[i];
}

// ---------------- dtype detect + CSR build ----------------
__global__ void k_detect(const int* ei) {
    if (threadIdx.x == 0 && blockIdx.x == 0) {
        int z = 0;
        for (int i = 1; i < 64; i += 2) z += (ei[i] == 0);
        g_is64 = (z == 32);
    }
}
__global__ void k_zero(int N) {
    int i = blockIdx.x * blockDim.x + threadIdx.x;
    if (i < N) g_cnt[i] = 0;
}
__global__ void k_hist(const void* ei, int E) {
    int e = blockIdx.x * blockDim.x + threadIdx.x;
    if (e < E) atomicAdd(&g_cnt[ld_idx(ei, (long long)E + e, g_is64)], 1);
}
__global__ void k_scan1(int N) {
    __shared__ int sh[1024];
    int t = threadIdx.x, i = blockIdx.x * 1024 + t;
    int v = (i < N) ? g_cnt[i] : 0;
    int x = v; sh[t] = x; __syncthreads();
    for (int off = 1; off < 1024; off <<= 1) {
        int add = (t >= off) ? sh[t - off] : 0;
        __syncthreads();
        x += add; sh[t] = x;
        __syncthreads();
    }
    if (i < N) g_rowptr[i] = x - v;
    if (t == 1023) g_blk[blockIdx.x] = x;
}
__global__ void k_scan2(int nb) {
    if (threadIdx.x == 0 && blockIdx.x == 0) {
        int acc = 0;
        for (int b = 0; b < nb; ++b) { int t = g_blk[b]; g_blk[b] = acc; acc += t; }
    }
}
__global__ void k_scan3(int N, int E) {
    int i = blockIdx.x * blockDim.x + threadIdx.x;
    if (i < N) {
        int v = g_rowptr[i] + g_blk[i >> 10];
        g_rowptr[i] = v; g_cur[i] = v;
    }
    if (i == 0) g_rowptr[N] = E;
}
__global__ void k_scatter(const void* ei, const void* et, int E) {
    int e = blockIdx.x * blockDim.x + threadIdx.x;
    if (e >= E) return;
    int is64 = g_is64;
    int s = ld_idx(ei, e, is64);
    int d = ld_idx(ei, (long long)E + e, is64);
    int t = ld_idx(et, e, is64);
    int pos = atomicAdd(&g_cur[d], 1);
    g_pse[pos] = make_int2(s, t);
}

// ---------------- hi/lo splits ----------------
__global__ void k_split(const float* __restrict__ a, __nv_bfloat16* __restrict__ hi,
                        __nv_bfloat16* __restrict__ lo, int n) {
    int i = blockIdx.x * blockDim.x + threadIdx.x;
    if (i >= n) return;
    float x = a[i];
    __nv_bfloat16 h = __float2bfloat16(x);
    hi[i] = h;
    lo[i] = __float2bfloat16(x - __bfloat162float(h));
}
// W[r][k][n] -> WT[(r*Ntot+n)*K + k] hi/lo
__global__ void k_splitW(const float* __restrict__ W, __nv_bfloat16* __restrict__ hi,
                         __nv_bfloat16* __restrict__ lo, int K, int Ntot, int total) {
    int i = blockIdx.x * blockDim.x + threadIdx.x;
    if (i >= total) return;
    int k = i % K;
    int rn = i / K;
    int n = rn % Ntot;
    int r = rn / Ntot;
    float x = W[((size_t)r * K + k) * Ntot + n];
    __nv_bfloat16 h = __float2bfloat16(x);
    hi[i] = h;
    lo[i] = __float2bfloat16(x - __bfloat162float(h));
}

// ---------------- fold attention vectors ----------------
__global__ void k_prep(const float* __restrict__ W, const float* __restrict__ as_,
                       const float* __restrict__ ad_, int K, int H, int C, int Wn) {
    int t = blockIdx.x * blockDim.x + threadIdx.x;
    if (t >= K * 64) return;
    int col = t & 63, k = t >> 6;
    int r = col >> 3, q = col & 7, h = q & 3;
    float acc = 0.f;
    if (h < H) {
        const float* av = ((q & 4) ? ad_ : as_) + h * C;
        const float* wp = W + ((size_t)r * K + k) * Wn + h * C;
        for (int c = 0; c < C; ++c) acc += wp[c] * av[c];
    }
    __nv_bfloat16 hb = __float2bfloat16(acc);
    g_wsdthi[col * K + k] = hb;
    g_wsdtlo[col * K + k] = __float2bfloat16(acc - __bfloat162float(hb));
}

// ============ big-tile GEMM: BM=256, BN=128, 512 threads ============
// smem stage (words): AsH 256*20 | AsL 256*20 | BsH 128*20 | BsL 128*20
#define ST2 15360
#define SMEM2 (size_t)(2 * ST2 * 4)

__device__ __forceinline__ void load_tile2(
    uint32_t* base, int tid, int m0, int M, int K, int kof, int n0,
    const __nv_bfloat16* Ahi, const __nv_bfloat16* Alo,
    const __nv_bfloat16* Bhi, const __nv_bfloat16* Blo) {
#pragma unroll
    for (int i = 0; i < 4; ++i) {
        int idx = tid + i * 512;
        int half = idx >> 10, rem = idx & 1023;
        int row = rem >> 2, ch = rem & 3;
        int gr = m0 + row;
        const __nv_bfloat16* p = (half ? Alo : Ahi) + (size_t)(gr < M ? gr : 0) * K + kof + ch * 8;
        uint32_t dst = (uint32_t)__cvta_generic_to_shared(base + half * 5120 + row * 20 + ch * 4);
        int sz = (gr < M) ? 16 : 0;
        asm volatile("cp.async.cg.shared.global [%0], [%1], 16, %2;"
                     :: "r"(dst), "l"(p), "r"(sz));
    }
#pragma unroll
    for (int i = 0; i < 2; ++i) {
        int idx = tid + i * 512;
        int half = idx >> 9, rem = idx & 511;
        int col = rem >> 2, ch = rem & 3;
        const __nv_bfloat16* p = (half ? Blo : Bhi) + (size_t)(n0 + col) * K + kof + ch * 8;
        uint32_t dst = (uint32_t)__cvta_generic_to_shared(base + 10240 + half * 2560 + col * 20 + ch * 4);
        asm volatile("cp.async.cg.shared.global [%0], [%1], 16;" :: "r"(dst), "l"(p));
    }
    asm volatile("cp.async.commit_group;");
}

__global__ __launch_bounds__(512, 1) void k_gemm2(
    const __nv_bfloat16* __restrict__ Ahi, const __nv_bfloat16* __restrict__ Alo,
    const __nv_bfloat16* __restrict__ Bhi, const __nv_bfloat16* __restrict__ Blo,
    float* __restrict__ C, int M, int K, int crs) {
    extern __shared__ uint32_t sm[];
    const int tid = threadIdx.x;
    const int m0 = blockIdx.x * 256;
    const int n0 = blockIdx.y * 128;

    const int lane = tid & 31, wid = tid >> 5;
    const int gid = lane >> 2, tig = lane & 3;
    const int m_off = (wid & 7) * 32, n_off = (wid >> 3) * 64;

    float acc[2][8][4];
#pragma unroll
    for (int f = 0; f < 2; ++f)
#pragma unroll
        for (int n = 0; n < 8; ++n)
#pragma unroll
            for (int q = 0; q < 4; ++q) acc[f][n][q] = 0.f;

    const int nkt = K >> 5;
    load_tile2(sm, tid, m0, M, K, 0, n0, Ahi, Alo, Bhi, Blo);

    for (int kt = 0; kt < nkt; ++kt) {
        if (kt + 1 < nkt) {
            load_tile2(sm + ((kt + 1) & 1) * ST2, tid, m0, M, K, (kt + 1) * 32, n0,
                       Ahi, Alo, Bhi, Blo);
            asm volatile("cp.async.wait_group 1;");
        } else {
            asm volatile("cp.async.wait_group 0;");
        }
        __syncthreads();
        const uint32_t* base = sm + (kt & 1) * ST2;
        const uint32_t* AsH = base;
        const uint32_t* AsL = base + 5120;
        const uint32_t* BsH = base + 10240;
        const uint32_t* BsL = base + 12800;
#pragma unroll
        for (int ks = 0; ks < 2; ++ks) {
            uint32_t aH[2][4], aL[2][4];
#pragma unroll
            for (int f = 0; f < 2; ++f) {
                int ro = (m_off + f * 16 + gid) * 20 + ks * 8 + tig;
                aH[f][0] = AsH[ro];           aH[f][1] = AsH[ro + 160];
                aH[f][2] = AsH[ro + 4];       aH[f][3] = AsH[ro + 164];
                aL[f][0] = AsL[ro];           aL[f][1] = AsL[ro + 160];
                aL[f][2] = AsL[ro + 4];       aL[f][3] = AsL[ro + 164];
            }
#pragma unroll
            for (int nf = 0; nf < 8; ++nf) {
                int bo = (n_off + nf * 8 + gid) * 20 + ks * 8 + tig;
                uint32_t bh0 = BsH[bo], bh1 = BsH[bo + 4];
                uint32_t bl0 = BsL[bo], bl1 = BsL[bo + 4];
                mma_bf16(acc[0][nf], aH[0], bh0, bh1);
                mma_bf16(acc[1][nf], aH[1], bh0, bh1);
                mma_bf16(acc[0][nf], aH[0], bl0, bl1);
                mma_bf16(acc[1][nf], aH[1], bl0, bl1);
                mma_bf16(acc[0][nf], aL[0], bh0, bh1);
                mma_bf16(acc[1][nf], aL[1], bh0, bh1);
            }
        }
        __syncthreads();
    }
#pragma unroll
    for (int f = 0; f < 2; ++f) {
        int row = m0 + m_off + f * 16 + gid;
#pragma unroll
        for (int nf = 0; nf < 8; ++nf) {
            int col = n0 + n_off + nf * 8 + 2 * tig;
            if (row < M)
                *(float2*)(C + (size_t)row * crs + col) =
                    make_float2(acc[f][nf][0], acc[f][nf][1]);
            if (row + 8 < M)
                *(float2*)(C + (size_t)(row + 8) * crs + col) =
                    make_float2(acc[f][nf][2], acc[f][nf][3]);
        }
    }
}

// ============ small GEMM for sd (BM=128, BN=64, 256 thr) ============
#define ST_WORDS 7680
#define GEMM_SMEM (size_t)(2 * ST_WORDS * 4)

__device__ __forceinline__ void gemm_load_tile(
    uint32_t* base, int tid, int m0, int M, int K, int kof,
    const __nv_bfloat16* Ahi, const __nv_bfloat16* Alo,
    const __nv_bfloat16* BhiG, const __nv_bfloat16* BloG) {
#pragma unroll
    for (int i = 0; i < 4; ++i) {
        int idx = tid + i * 256;
        int half = idx >> 9, rem = idx & 511;
        int row = rem >> 2, ch = rem & 3;
        int gr = m0 + row;
        const __nv_bfloat16* src = half ? Alo : Ahi;
        const __nv_bfloat16* p = src + (size_t)(gr < M ? gr : 0) * K + kof + ch * 8;
        uint32_t dst = (uint32_t)__cvta_generic_to_shared(base + half * 2560 + row * 20 + ch * 4);
        int sz = (gr < M) ? 16 : 0;
        asm volatile("cp.async.cg.shared.global [%0], [%1], 16, %2;"
                     :: "r"(dst), "l"(p), "r"(sz));
    }
#pragma unroll
    for (int i = 0; i < 2; ++i) {
        int idx = tid + i * 256;
        int half = idx >> 8, rem = idx & 255;
        int col = rem >> 2, ch = rem & 3;
        const __nv_bfloat16* p = (half ? BloG : BhiG) + (size_t)col * K + kof + ch * 8;
        uint32_t dst = (uint32_t)__cvta_generic_to_shared(base + 5120 + half * 1280 + col * 20 + ch * 4);
        asm volatile("cp.async.cg.shared.global [%0], [%1], 16;" :: "r"(dst), "l"(p));
    }
    asm volatile("cp.async.commit_group;");
}

__global__ __launch_bounds__(256, 2) void k_gemm(
    const __nv_bfloat16* __restrict__ Ahi, const __nv_bfloat16* __restrict__ Alo,
    const __nv_bfloat16* __restrict__ Bhi, const __nv_bfloat16* __restrict__ Blo,
    float* __restrict__ C, int M, int K, int crs) {
    extern __shared__ uint32_t sm[];
    const int tid = threadIdx.x;
    const int m0 = blockIdx.x * 128;
    const __nv_bfloat16* BhiG = Bhi;
    const __nv_bfloat16* BloG = Blo;

    const int lane = tid & 31, wid = tid >> 5;
    const int gid = lane >> 2, tig = lane & 3;
    const int m_off = (wid & 3) * 32, n_off = (wid >> 2) * 32;

    float acc[2][4][4];
#pragma unroll
    for (int f = 0; f < 2; ++f)
#pragma unroll
        for (int n = 0; n < 4; ++n)
#pragma unroll
            for (int q = 0; q < 4; ++q) acc[f][n][q] = 0.f;

    const int nkt = K >> 5;
    gemm_load_tile(sm, tid, m0, M, K, 0, Ahi, Alo, BhiG, BloG);

    for (int kt = 0; kt < nkt; ++kt) {
        if (kt + 1 < nkt) {
            gemm_load_tile(sm + ((kt + 1) & 1) * ST_WORDS, tid, m0, M, K,
                           (kt + 1) * 32, Ahi, Alo, BhiG, BloG);
            asm volatile("cp.async.wait_group 1;");
        } else {
            asm volatile("cp.async.wait_group 0;");
        }
        __syncthreads();
        const uint32_t* base = sm + (kt & 1) * ST_WORDS;
        const uint32_t* AsH = base;
        const uint32_t* AsL = base + 2560;
        const uint32_t* BsH = base + 5120;
        const uint32_t* BsL = base + 6400;
#pragma unroll
        for (int ks = 0; ks < 2; ++ks) {
            uint32_t aH[2][4], aL[2][4];
#pragma unroll
            for (int f = 0; f < 2; ++f) {
                int ro = (m_off + f * 16 + gid) * 20 + ks * 8 + tig;
                aH[f][0] = AsH[ro];           aH[f][1] = AsH[ro + 160];
                aH[f][2] = AsH[ro + 4];       aH[f][3] = AsH[ro + 164];
                aL[f][0] = AsL[ro];           aL[f][1] = AsL[ro + 160];
                aL[f][2] = AsL[ro + 4];       aL[f][3] = AsL[ro + 164];
            }
#pragma unroll
            for (int nf = 0; nf < 4; ++nf) {
                int bo = (n_off + nf * 8 + gid) * 20 + ks * 8 + tig;
                uint32_t bh0 = BsH[bo], bh1 = BsH[bo + 4];
                uint32_t bl0 = BsL[bo], bl1 = BsL[bo + 4];
                mma_bf16(acc[0][nf], aH[0], bh0, bh1);
                mma_bf16(acc[1][nf], aH[1], bh0, bh1);
                mma_bf16(acc[0][nf], aH[0], bl0, bl1);
                mma_bf16(acc[1][nf], aH[1], bl0, bl1);
                mma_bf16(acc[0][nf], aL[0], bh0, bh1);
                mma_bf16(acc[1][nf], aL[1], bh0, bh1);
            }
        }
        __syncthreads();
    }
#pragma unroll
    for (int f = 0; f < 2; ++f) {
        int row = m0 + m_off + f * 16 + gid;
#pragma unroll
        for (int nf = 0; nf < 4; ++nf) {
            int col = n_off + nf * 8 + 2 * tig;
            if (row < M)
                *(float2*)(C + (size_t)row * crs + col) =
                    make_float2(acc[f][nf][0], acc[f][nf][1]);
            if (row + 8 < M)
                *(float2*)(C + (size_t)(row + 8) * crs + col) =
                    make_float2(acc[f][nf][2], acc[f][nf][3]);
        }
    }
}

// ---------------- aggregation (online softmax, fused LN+ELU+split) ----------------
template <int H>
__device__ __forceinline__ void get_alpha(const float* __restrict__ sd,
                                          const float* __restrict__ ar,
                                          int dst, int s, int t, float* a) {
    if (H == 4) {
        float4 sv = *(const float4*)(sd + (size_t)s * 64 + t * 8);
        float4 dv = *(const float4*)(sd + (size_t)dst * 64 + t * 8 + 4);
        float4 av = *(const float4*)(ar + t * 4);
        a[0] = sv.x + dv.x + av.x; a[1] = sv.y + dv.y + av.y;
        a[2] = sv.z + dv.z + av.z; a[3] = sv.w + dv.w + av.w;
    } else {
        a[0] = sd[(size_t)s * 64 + t * 8] + sd[(size_t)dst * 64 + t * 8 + 4] + ar[t];
    }
#pragma unroll
    for (int h = 0; h < H; ++h) a[h] = a[h] > 0.f ? a[h] : 0.2f * a[h];
}

template <int CPL, bool LN>
__global__ __launch_bounds__(256) void k_agg(
    const float* __restrict__ xw, const float* __restrict__ sd,
    const float* __restrict__ ar, const float* __restrict__ bias,
    const float* __restrict__ gamma, const float* __restrict__ beta,
    float* __restrict__ out, __nv_bfloat16* __restrict__ ohi,
    __nv_bfloat16* __restrict__ olo, int N, int xws, int rls) {
    constexpr int H = CPL * 32 / 64;
    constexpr int OUT = CPL * 32;
    __shared__ float walpha[8][32][4];
    int w = (blockIdx.x * blockDim.x + threadIdx.x) >> 5;
    if (w >= N) return;
    int lane = threadIdx.x & 31, wl = threadIdx.x >> 5;
    int hh = (lane * CPL) >> 6;
    int beg = g_rowptr[w], end = g_rowptr[w + 1];

    float mx[H], dn[H];
#pragma unroll
    for (int h = 0; h < H; ++h) { mx[h] = -1e30f; dn[h] = 0.f; }
    for (int e = beg + lane; e < end; e += 32) {
        int2 pe = g_pse[e];
        float a[H];
        get_alpha<H>(sd, ar, w, pe.x, pe.y, a);
#pragma unroll
        for (int h = 0; h < H; ++h) {
            float mn = fmaxf(mx[h], a[h]);
            dn[h] = dn[h] * __expf(mx[h] - mn) + __expf(a[h] - mn);
            mx[h] = mn;
        }
    }
#pragma unroll
    for (int h = 0; h < H; ++h) {
#pragma unroll
        for (int o = 16; o; o >>= 1) {
            float mo = __shfl_xor_sync(0xffffffffu, mx[h], o);
            float dd = __shfl_xor_sync(0xffffffffu, dn[h], o);
            float mn = fmaxf(mx[h], mo);
            dn[h] = dn[h] * __expf(mx[h] - mn) + dd * __expf(mo - mn);
            mx[h] = mn;
        }
        dn[h] = 1.f / dn[h];
    }

    float acc[CPL];
#pragma unroll
    for (int c = 0; c < CPL; ++c) acc[c] = 0.f;

    for (int base = beg; base < end; base += 32) {
        int e = base + lane;
        int cnt = min(32, end - base);
        int sR = 0, tR = 0;
        if (e < end) {
            int2 pe = g_pse[e];
            sR = pe.x; tR = pe.y;
            float a[H];
            get_alpha<H>(sd, ar, w, sR, tR, a);
#pragma unroll
            for (int h = 0; h < H; ++h)
                walpha[wl][lane][h] = __expf(a[h] - mx[h]) * dn[h];
        }
        __syncwarp();
        for (int j = 0; j < cnt; ++j) {
            int s = __shfl_sync(0xffffffffu, sR, j);
            int t = __shfl_sync(0xffffffffu, tR, j);
            float wv = walpha[wl][j][hh];
            const float* p = xw + (size_t)s * xws + t * rls + lane * CPL;
            if (CPL == 8) {
                float4 v0 = *(const float4*)p, v1 = *(const float4*)(p + 4);
                acc[0] += wv * v0.x; acc[1] += wv * v0.y;
                acc[2] += wv * v0.z; acc[3] += wv * v0.w;
                acc[4] += wv * v1.x; acc[5] += wv * v1.y;
                acc[6] += wv * v1.z; acc[7] += wv * v1.w;
            } else {
                float2 v = *(const float2*)p;
                acc[0] += wv * v.x; acc[1] += wv * v.y;
            }
        }
        __syncwarp();
    }

    if (LN) {
        float4 b0 = *(const float4*)(bias + lane * 8);
        float4 b1 = *(const float4*)(bias + lane * 8 + 4);
        acc[0] += b0.x; acc[1] += b0.y; acc[2] += b0.z; acc[3] += b0.w;
        acc[4] += b1.x; acc[5] += b1.y; acc[6] += b1.z; acc[7] += b1.w;
        float s1 = 0.f;
#pragma unroll
        for (int c = 0; c < CPL; ++c) s1 += acc[c];
#pragma unroll
        for (int o = 16; o; o >>= 1) s1 += __shfl_xor_sync(0xffffffffu, s1, o);
        float m = s1 / (float)OUT;
        float s2 = 0.f;
#pragma unroll
        for (int c = 0; c < CPL; ++c) { float d = acc[c] - m; s2 += d * d; }
#pragma unroll
        for (int o = 16; o; o >>= 1) s2 += __shfl_xor_sync(0xffffffffu, s2, o);
        float rstd = rsqrtf(s2 / (float)OUT + 1e-5f);
        float4 gA = *(const float4*)(gamma + lane * 8);
        float4 gB = *(const float4*)(gamma + lane * 8 + 4);
        float4 tA = *(const float4*)(beta + lane * 8);
        float4 tB = *(const float4*)(beta + lane * 8 + 4);
        float gm[8] = {gA.x, gA.y, gA.z, gA.w, gB.x, gB.y, gB.z, gB.w};
        float bt[8] = {tA.x, tA.y, tA.z, tA.w, tB.x, tB.y, tB.z, tB.w};
        __nv_bfloat16 hv[8], lv[8];
#pragma unroll
        for (int c = 0; c < 8; ++c) {
            float y = gm[c] * (acc[c] - m) * rstd + bt[c];
            y = y > 0.f ? y : (expf(y) - 1.f);
            hv[c] = __float2bfloat16(y);
            lv[c] = __float2bfloat16(y - __bfloat162float(hv[c]));
        }
        *(float4*)(ohi + (size_t)w * OUT + lane * 8) = *(float4*)hv;
        *(float4*)(olo + (size_t)w * OUT + lane * 8) = *(float4*)lv;
    } else {
        out[(size_t)w * OUT + lane * 2] = acc[0] + bias[lane * 2];
        out[(size_t)w * OUT + lane * 2 + 1] = acc[1] + bias[lane * 2 + 1];
    }
}

// ---------------- launch ----------------
extern "C" void kernel_launch(void* const* d_in, const int* in_sizes, int n_in,
                              void* d_out, int out_size) {
    const float* x   = (const float*)d_in[0];
    const void*  ei  = d_in[1];
    const void*  et  = d_in[2];
    const float* W0  = (const float*)d_in[3];
    const float* as0 = (const float*)d_in[4];
    const float* ad0 = (const float*)d_in[5];
    const float* ar0 = (const float*)d_in[6];
    const float* bi0 = (const float*)d_in[7];
    const float* W1  = (const float*)d_in[8];
    const float* as1 = (const float*)d_in[9];
    const float* ad1 = (const float*)d_in[10];
    const float* ar1 = (const float*)d_in[11];
    const float* bi1 = (const float*)d_in[12];
    const float* W2  = (const float*)d_in[13];
    const float* as2 = (const float*)d_in[14];
    const float* ad2 = (const float*)d_in[15];
    const float* ar2 = (const float*)d_in[16];
    const float* bi2 = (const float*)d_in[17];
    const float* g0  = (const float*)d_in[18];
    const float* be0 = (const float*)d_in[19];
    const float* g1  = (const float*)d_in[20];
    const float* be1 = (const float*)d_in[21];

    const int N = in_sizes[0] / 128;        // 50000
    const int E = in_sizes[2];              // 800000
    float* out = (float*)d_out;

    float *xw, *sd;
    __nv_bfloat16 *ahi, *alo, *wthi, *wtlo, *wsdthi, *wsdtlo;
    cudaGetSymbolAddress((void**)&xw, g_xw);
    cudaGetSymbolAddress((void**)&sd, g_sd);
    cudaGetSymbolAddress((void**)&ahi, g_ahi);
    cudaGetSymbolAddress((void**)&alo, g_alo);
    cudaGetSymbolAddress((void**)&wthi, g_wthi);
    cudaGetSymbolAddress((void**)&wtlo, g_wtlo);
    cudaGetSymbolAddress((void**)&wsdthi, g_wsdthi);
    cudaGetSymbolAddress((void**)&wsdtlo, g_wsdtlo);

    static int smem_set = 0;
    if (!smem_set) {
        cudaFuncSetAttribute(k_gemm, cudaFuncAttributeMaxDynamicSharedMemorySize,
                             (int)GEMM_SMEM);
        cudaFuncSetAttribute(k_gemm2, cudaFuncAttributeMaxDynamicSharedMemorySize,
                             (int)SMEM2);
        smem_set = 1;
    }

    const int MB = (N + 127) / 128;         // 391
    const int MB2 = (N + 255) / 256;        // 196
    const int EB = (E + 255) / 256;
    const int NB = (N + 255) / 256;
    const int SB = (N + 1023) / 1024;

    // ---- layer 0 dense front (big GEMM early for ncu window) ----
    k_split<<<(N * 128 + 255) / 256, 256>>>(x, ahi, alo, N * 128);
    k_splitW<<<(8 * 128 * 256 + 255) / 256, 256>>>(W0, wthi, wtlo, 128, 256, 8 * 128 * 256);
    k_prep<<<(128 * 64 + 255) / 256, 256>>>(W0, as0, ad0, 128, 4, 64, 256);
    k_gemm2<<<dim3(MB2, 16), 512, SMEM2>>>(ahi, alo, wthi, wtlo, xw, N, 128, 2048);
    k_gemm<<<dim3(MB, 1), 256, GEMM_SMEM>>>(ahi, alo, wsdthi, wsdtlo, sd, N, 128, 64);

    // ---- CSR build ----
    k_detect<<<1, 32>>>((const int*)ei);
    k_zero<<<NB, 256>>>(N);
    k_hist<<<EB, 256>>>(ei, E);
    k_scan1<<<SB, 1024>>>(N);
    k_scan2<<<1, 1>>>(SB);
    k_scan3<<<NB, 256>>>(N, E);
    k_scatter<<<EB, 256>>>(ei, et, E);

    k_agg<8, true><<<(N * 32 + 255) / 256, 256>>>(xw, sd, ar0, bi0, g0, be0,
                                                  nullptr, ahi, alo, N, 2048, 256);

    // ---- layer 1 (K=256) ----
    k_splitW<<<(8 * 256 * 256 + 255) / 256, 256>>>(W1, wthi, wtlo, 256, 256, 8 * 256 * 256);
    k_prep<<<(256 * 64 + 255) / 256, 256>>>(W1, as1, ad1, 256, 4, 64, 256);
    k_gemm<<<dim3(MB, 1), 256, GEMM_SMEM>>>(ahi, alo, wsdthi, wsdtlo, sd, N, 256, 64);
    k_gemm2<<<dim3(MB2, 16), 512, SMEM2>>>(ahi, alo, wthi, wtlo, xw, N, 256, 2048);
    k_agg<8, true><<<(N * 32 + 255) / 256, 256>>>(xw, sd, ar1, bi1, g1, be1,
                                                  nullptr, ahi, alo, N, 2048, 256);

    // ---- layer 2 (K=256, G=512) ----
    k_splitW<<<(8 * 256 * 64 + 255) / 256, 256>>>(W2, wthi, wtlo, 256, 64, 8 * 256 * 64);
    k_prep<<<(256 * 64 + 255) / 256, 256>>>(W2, as2, ad2, 256, 1, 64, 64);
    k_gemm<<<dim3(MB, 1), 256, GEMM_SMEM>>>(ahi, alo, wsdthi, wsdtlo, sd, N, 256, 64);
    k_gemm2<<<dim3(MB2, 4), 512, SMEM2>>>(ahi, alo, wthi, wtlo, xw, N, 256, 512);
    k_agg<2, false><<<(N * 32 + 255) / 256, 256>>>(xw, sd, ar2, bi2, nullptr, nullptr,
                                                   out, nullptr, nullptr, N, 512, 64);
}

// round 13
// speedup vs baseline: 1.4568x; 1.0011x over previous
#include <cuda_runtime.h>
#include <cuda_bf16.h>
#include <cstdint>
#include <cstddef>

// RGAT 3-layer on GB300 (legacy mma.sync path — tcgen05 unsupported by harness
// toolchain). Weights stored as ONE global col-major matrix of G columns.
//  gemm:  3xBF16 m16n8k16 (hi*hi + hi*lo + lo*hi), cp.async double-buffered.
//         MMA emission is TERM-OUTERMOST: 8 independent-accumulator MMAs per
//         term, so accumulator RAW reuse distance is 8 MMAs (~64 cyc) >> HMMA
//         latency — kills the short-scoreboard stalls that capped tensor at 46%.
//  agg :  CSR(warp-per-dst) online softmax + gather-sum, fused bias+LN+ELU,
//         epilogue emits next layer's (hi,lo) bf16 directly.

__device__ float g_xw[102400000];           // 50000*2048
__device__ float g_sd[3200000];             // 50000*64
__device__ __nv_bfloat16 g_ahi[12800000];   // 50000*256
__device__ __nv_bfloat16 g_alo[12800000];
__device__ __nv_bfloat16 g_wthi[524288];    // 8*256*256 (global col-major)
__device__ __nv_bfloat16 g_wtlo[524288];
__device__ __nv_bfloat16 g_wsdthi[16384];   // 64*256
__device__ __nv_bfloat16 g_wsdtlo[16384];
__device__ int   g_cnt[50000];
__device__ int   g_rowptr[50001];
__device__ int   g_cur[50000];
__device__ int2  g_pse[800000];             // (src, etype)
__device__ int   g_blk[64];
__device__ int   g_is64;

__device__ __forceinline__ void mma_bf16(float c[4], const uint32_t a[4],
                                         uint32_t b0, uint32_t b1) {
    asm volatile(
        "mma.sync.aligned.m16n8k16.row.col.f32.bf16.bf16.f32 "
        "{%0,%1,%2,%3},{%4,%5,%6,%7},{%8,%9},{%0,%1,%2,%3};"
        : "+f"(c[0]), "+f"(c[1]), "+f"(c[2]), "+f"(c[3])
        : "r"(a[0]), "r"(a[1]), "r"(a[2]), "r"(a[3]), "r"(b0), "r"(b1));
}
__device__ __forceinline__ int ld_idx(const void* p, long long i, int is64) {
    return is64 ? (int)((const long long*)p)[i] : ((const int*)p)[i];
}

// ---------------- dtype detect + CSR build ----------------
__global__ void k_detect(const int* ei) {
    if (threadIdx.x == 0 && blockIdx.x == 0) {
        int z = 0;
        for (int i = 1; i < 64; i += 2) z += (ei[i] == 0);
        g_is64 = (z == 32);
    }
}
__global__ void k_zero(int N) {
    int i = blockIdx.x * blockDim.x + threadIdx.x;
    if (i < N) g_cnt[i] = 0;
}
__global__ void k_hist(const void* ei, int E) {
    int e = blockIdx.x * blockDim.x + threadIdx.x;
    if (e < E) atomicAdd(&g_cnt[ld_idx(ei, (long long)E + e, g_is64)], 1);
}
__global__ void k_scan1(int N) {
    __shared__ int sh[1024];
    int t = threadIdx.x, i = blockIdx.x * 1024 + t;
    int v = (i < N) ? g_cnt[i] : 0;
    int x = v; sh[t] = x; __syncthreads();
    for (int off = 1; off < 1024; off <<= 1) {
        int add = (t >= off) ? sh[t - off] : 0;
        __syncthreads();
        x += add; sh[t] = x;
        __syncthreads();
    }
    if (i < N) g_rowptr[i] = x - v;
    if (t == 1023) g_blk[blockIdx.x] = x;
}
__global__ void k_scan2(int nb) {
    if (threadIdx.x == 0 && blockIdx.x == 0) {
        int acc = 0;
        for (int b = 0; b < nb; ++b) { int t = g_blk[b]; g_blk[b] = acc; acc += t; }
    }
}
__global__ void k_scan3(int N, int E) {
    int i = blockIdx.x * blockDim.x + threadIdx.x;
    if (i < N) {
        int v = g_rowptr[i] + g_blk[i >> 10];
        g_rowptr[i] = v; g_cur[i] = v;
    }
    if (i == 0) g_rowptr[N] = E;
}
__global__ void k_scatter(const void* ei, const void* et, int E) {
    int e = blockIdx.x * blockDim.x + threadIdx.x;
    if (e >= E) return;
    int is64 = g_is64;
    int s = ld_idx(ei, e, is64);
    int d = ld_idx(ei, (long long)E + e, is64);
    int t = ld_idx(et, e, is64);
    int pos = atomicAdd(&g_cur[d], 1);
    g_pse[pos] = make_int2(s, t);
}

// ---------------- hi/lo splits ----------------
__global__ void k_split(const float* __restrict__ a, __nv_bfloat16* __restrict__ hi,
                        __nv_bfloat16* __restrict__ lo, int n) {
    int i = blockIdx.x * blockDim.x + threadIdx.x;
    if (i >= n) return;
    float x = a[i];
    __nv_bfloat16 h = __float2bfloat16(x);
    hi[i] = h;
    lo[i] = __float2bfloat16(x - __bfloat162float(h));
}
// W[r][k][n] -> WT[(r*Ntot+n)*K + k] hi/lo
__global__ void k_splitW(const float* __restrict__ W, __nv_bfloat16* __restrict__ hi,
                         __nv_bfloat16* __restrict__ lo, int K, int Ntot, int total) {
    int i = blockIdx.x * blockDim.x + threadIdx.x;
    if (i >= total) return;
    int k = i % K;
    int rn = i / K;
    int n = rn % Ntot;
    int r = rn / Ntot;
    float x = W[((size_t)r * K + k) * Ntot + n];
    __nv_bfloat16 h = __float2bfloat16(x);
    hi[i] = h;
    lo[i] = __float2bfloat16(x - __bfloat162float(h));
}

// ---------------- fold attention vectors ----------------
__global__ void k_prep(const float* __restrict__ W, const float* __restrict__ as_,
                       const float* __restrict__ ad_, int K, int H, int C, int Wn) {
    int t = blockIdx.x * blockDim.x + threadIdx.x;
    if (t >= K * 64) return;
    int col = t & 63, k = t >> 6;
    int r = col >> 3, q = col & 7, h = q & 3;
    float acc = 0.f;
    if (h < H) {
        const float* av = ((q & 4) ? ad_ : as_) + h * C;
        const float* wp = W + ((size_t)r * K + k) * Wn + h * C;
        for (int c = 0; c < C; ++c) acc += wp[c] * av[c];
    }
    __nv_bfloat16 hb = __float2bfloat16(acc);
    g_wsdthi[col * K + k] = hb;
    g_wsdtlo[col * K + k] = __float2bfloat16(acc - __bfloat162float(hb));
}

// ============ big-tile GEMM: BM=256, BN=128, 512 threads ============
// smem stage (words): AsH 256*20 | AsL 256*20 | BsH 128*20 | BsL 128*20
#define ST2 15360
#define SMEM2 (size_t)(2 * ST2 * 4)

__device__ __forceinline__ void load_tile2(
    uint32_t* base, int tid, int m0, int M, int K, int kof, int n0,
    const __nv_bfloat16* Ahi, const __nv_bfloat16* Alo,
    const __nv_bfloat16* Bhi, const __nv_bfloat16* Blo) {
#pragma unroll
    for (int i = 0; i < 4; ++i) {
        int idx = tid + i * 512;
        int half = idx >> 10, rem = idx & 1023;
        int row = rem >> 2, ch = rem & 3;
        int gr = m0 + row;
        const __nv_bfloat16* p = (half ? Alo : Ahi) + (size_t)(gr < M ? gr : 0) * K + kof + ch * 8;
        uint32_t dst = (uint32_t)__cvta_generic_to_shared(base + half * 5120 + row * 20 + ch * 4);
        int sz = (gr < M) ? 16 : 0;
        asm volatile("cp.async.cg.shared.global [%0], [%1], 16, %2;"
                     :: "r"(dst), "l"(p), "r"(sz));
    }
#pragma unroll
    for (int i = 0; i < 2; ++i) {
        int idx = tid + i * 512;
        int half = idx >> 9, rem = idx & 511;
        int col = rem >> 2, ch = rem & 3;
        const __nv_bfloat16* p = (half ? Blo : Bhi) + (size_t)(n0 + col) * K + kof + ch * 8;
        uint32_t dst = (uint32_t)__cvta_generic_to_shared(base + 10240 + half * 2560 + col * 20 + ch * 4);
        asm volatile("cp.async.cg.shared.global [%0], [%1], 16;" :: "r"(dst), "l"(p));
    }
    asm volatile("cp.async.commit_group;");
}

__global__ __launch_bounds__(512, 1) void k_gemm2(
    const __nv_bfloat16* __restrict__ Ahi, const __nv_bfloat16* __restrict__ Alo,
    const __nv_bfloat16* __restrict__ Bhi, const __nv_bfloat16* __restrict__ Blo,
    float* __restrict__ C, int M, int K, int crs) {
    extern __shared__ uint32_t sm[];
    const int tid = threadIdx.x;
    const int m0 = blockIdx.x * 256;
    const int n0 = blockIdx.y * 128;

    const int lane = tid & 31, wid = tid >> 5;
    const int gid = lane >> 2, tig = lane & 3;
    const int m_off = (wid & 7) * 32, n_off = (wid >> 3) * 64;

    float acc[2][8][4];
#pragma unroll
    for (int f = 0; f < 2; ++f)
#pragma unroll
        for (int n = 0; n < 8; ++n)
#pragma unroll
            for (int q = 0; q < 4; ++q) acc[f][n][q] = 0.f;

    const int nkt = K >> 5;
    load_tile2(sm, tid, m0, M, K, 0, n0, Ahi, Alo, Bhi, Blo);

    for (int kt = 0; kt < nkt; ++kt) {
        if (kt + 1 < nkt) {
            load_tile2(sm + ((kt + 1) & 1) * ST2, tid, m0, M, K, (kt + 1) * 32, n0,
                       Ahi, Alo, Bhi, Blo);
            asm volatile("cp.async.wait_group 1;");
        } else {
            asm volatile("cp.async.wait_group 0;");
        }
        __syncthreads();
        const uint32_t* base = sm + (kt & 1) * ST2;
        const uint32_t* AsH = base;
        const uint32_t* AsL = base + 5120;
        const uint32_t* BsH = base + 10240;
        const uint32_t* BsL = base + 12800;
#pragma unroll
        for (int ks = 0; ks < 2; ++ks) {
            uint32_t aH[2][4], aL[2][4];
#pragma unroll
            for (int f = 0; f < 2; ++f) {
                int ro = (m_off + f * 16 + gid) * 20 + ks * 8 + tig;
                aH[f][0] = AsH[ro];           aH[f][1] = AsH[ro + 160];
                aH[f][2] = AsH[ro + 4];       aH[f][3] = AsH[ro + 164];
                aL[f][0] = AsL[ro];           aL[f][1] = AsL[ro + 160];
                aL[f][2] = AsL[ro + 4];       aL[f][3] = AsL[ro + 164];
            }
            // nf in halves of 4; within each half, term-outermost emission:
            // 8 independent MMAs per term -> acc reuse distance = 8 MMAs.
#pragma unroll
            for (int hf = 0; hf < 2; ++hf) {
                uint32_t bh[4][2], bl[4][2];
#pragma unroll
                for (int j = 0; j < 4; ++j) {
                    int bo = (n_off + (hf * 4 + j) * 8 + gid) * 20 + ks * 8 + tig;
                    bh[j][0] = BsH[bo]; bh[j][1] = BsH[bo + 4];
                    bl[j][0] = BsL[bo]; bl[j][1] = BsL[bo + 4];
                }
#pragma unroll
                for (int j = 0; j < 4; ++j) {
                    mma_bf16(acc[0][hf * 4 + j], aH[0], bh[j][0], bh[j][1]);
                    mma_bf16(acc[1][hf * 4 + j], aH[1], bh[j][0], bh[j][1]);
                }
#pragma unroll
                for (int j = 0; j < 4; ++j) {
                    mma_bf16(acc[0][hf * 4 + j], aH[0], bl[j][0], bl[j][1]);
                    mma_bf16(acc[1][hf * 4 + j], aH[1], bl[j][0], bl[j][1]);
                }
#pragma unroll
                for (int j = 0; j < 4; ++j) {
                    mma_bf16(acc[0][hf * 4 + j], aL[0], bh[j][0], bh[j][1]);
                    mma_bf16(acc[1][hf * 4 + j], aL[1], bh[j][0], bh[j][1]);
                }
            }
        }
        __syncthreads();
    }
#pragma unroll
    for (int f = 0; f < 2; ++f) {
        int row = m0 + m_off + f * 16 + gid;
#pragma unroll
        for (int nf = 0; nf < 8; ++nf) {
            int col = n0 + n_off + nf * 8 + 2 * tig;
            if (row < M)
                *(float2*)(C + (size_t)row * crs + col) =
                    make_float2(acc[f][nf][0], acc[f][nf][1]);
            if (row + 8 < M)
                *(float2*)(C + (size_t)(row + 8) * crs + col) =
                    make_float2(acc[f][nf][2], acc[f][nf][3]);
        }
    }
}

// ============ small GEMM for sd (BM=128, BN=64, 256 thr) ============
#define ST_WORDS 7680
#define GEMM_SMEM (size_t)(2 * ST_WORDS * 4)

__device__ __forceinline__ void gemm_load_tile(
    uint32_t* base, int tid, int m0, int M, int K, int kof,
    const __nv_bfloat16* Ahi, const __nv_bfloat16* Alo,
    const __nv_bfloat16* BhiG, const __nv_bfloat16* BloG) {
#pragma unroll
    for (int i = 0; i < 4; ++i) {
        int idx = tid + i * 256;
        int half = idx >> 9, rem = idx & 511;
        int row = rem >> 2, ch = rem & 3;
        int gr = m0 + row;
        const __nv_bfloat16* src = half ? Alo : Ahi;
        const __nv_bfloat16* p = src + (size_t)(gr < M ? gr : 0) * K + kof + ch * 8;
        uint32_t dst = (uint32_t)__cvta_generic_to_shared(base + half * 2560 + row * 20 + ch * 4);
        int sz = (gr < M) ? 16 : 0;
        asm volatile("cp.async.cg.shared.global [%0], [%1], 16, %2;"
                     :: "r"(dst), "l"(p), "r"(sz));
    }
#pragma unroll
    for (int i = 0; i < 2; ++i) {
        int idx = tid + i * 256;
        int half = idx >> 8, rem = idx & 255;
        int col = rem >> 2, ch = rem & 3;
        const __nv_bfloat16* p = (half ? BloG : BhiG) + (size_t)col * K + kof + ch * 8;
        uint32_t dst = (uint32_t)__cvta_generic_to_shared(base + 5120 + half * 1280 + col * 20 + ch * 4);
        asm volatile("cp.async.cg.shared.global [%0], [%1], 16;" :: "r"(dst), "l"(p));
    }
    asm volatile("cp.async.commit_group;");
}

__global__ __launch_bounds__(256, 2) void k_gemm(
    const __nv_bfloat16* __restrict__ Ahi, const __nv_bfloat16* __restrict__ Alo,
    const __nv_bfloat16* __restrict__ Bhi, const __nv_bfloat16* __restrict__ Blo,
    float* __restrict__ C, int M, int K, int crs) {
    extern __shared__ uint32_t sm[];
    const int tid = threadIdx.x;
    const int m0 = blockIdx.x * 128;

    const int lane = tid & 31, wid = tid >> 5;
    const int gid = lane >> 2, tig = lane & 3;
    const int m_off = (wid & 3) * 32, n_off = (wid >> 2) * 32;

    float acc[2][4][4];
#pragma unroll
    for (int f = 0; f < 2; ++f)
#pragma unroll
        for (int n = 0; n < 4; ++n)
#pragma unroll
            for (int q = 0; q < 4; ++q) acc[f][n][q] = 0.f;

    const int nkt = K >> 5;
    gemm_load_tile(sm, tid, m0, M, K, 0, Ahi, Alo, Bhi, Blo);

    for (int kt = 0; kt < nkt; ++kt) {
        if (kt + 1 < nkt) {
            gemm_load_tile(sm + ((kt + 1) & 1) * ST_WORDS, tid, m0, M, K,
                           (kt + 1) * 32, Ahi, Alo, Bhi, Blo);
            asm volatile("cp.async.wait_group 1;");
        } else {
            asm volatile("cp.async.wait_group 0;");
        }
        __syncthreads();
        const uint32_t* base = sm + (kt & 1) * ST_WORDS;
        const uint32_t* AsH = base;
        const uint32_t* AsL = base + 2560;
        const uint32_t* BsH = base + 5120;
        const uint32_t* BsL = base + 6400;
#pragma unroll
        for (int ks = 0; ks < 2; ++ks) {
            uint32_t aH[2][4], aL[2][4];
#pragma unroll
            for (int f = 0; f < 2; ++f) {
                int ro = (m_off + f * 16 + gid) * 20 + ks * 8 + tig;
                aH[f][0] = AsH[ro];           aH[f][1] = AsH[ro + 160];
                aH[f][2] = AsH[ro + 4];       aH[f][3] = AsH[ro + 164];
                aL[f][0] = AsL[ro];           aL[f][1] = AsL[ro + 160];
                aL[f][2] = AsL[ro + 4];       aL[f][3] = AsL[ro + 164];
            }
            uint32_t bh[4][2], bl[4][2];
#pragma unroll
            for (int j = 0; j < 4; ++j) {
                int bo = (n_off + j * 8 + gid) * 20 + ks * 8 + tig;
                bh[j][0] = BsH[bo]; bh[j][1] = BsH[bo + 4];
                bl[j][0] = BsL[bo]; bl[j][1] = BsL[bo + 4];
            }
#pragma unroll
            for (int j = 0; j < 4; ++j) {
                mma_bf16(acc[0][j], aH[0], bh[j][0], bh[j][1]);
                mma_bf16(acc[1][j], aH[1], bh[j][0], bh[j][1]);
            }
#pragma unroll
            for (int j = 0; j < 4; ++j) {
                mma_bf16(acc[0][j], aH[0], bl[j][0], bl[j][1]);
                mma_bf16(acc[1][j], aH[1], bl[j][0], bl[j][1]);
            }
#pragma unroll
            for (int j = 0; j < 4; ++j) {
                mma_bf16(acc[0][j], aL[0], bh[j][0], bh[j][1]);
                mma_bf16(acc[1][j], aL[1], bh[j][0], bh[j][1]);
            }
        }
        __syncthreads();
    }
#pragma unroll
    for (int f = 0; f < 2; ++f) {
        int row = m0 + m_off + f * 16 + gid;
#pragma unroll
        for (int nf = 0; nf < 4; ++nf) {
            int col = n_off + nf * 8 + 2 * tig;
            if (row < M)
                *(float2*)(C + (size_t)row * crs + col) =
                    make_float2(acc[f][nf][0], acc[f][nf][1]);
            if (row + 8 < M)
                *(float2*)(C + (size_t)(row + 8) * crs + col) =
                    make_float2(acc[f][nf][2], acc[f][nf][3]);
        }
    }
}

// ---------------- aggregation (online softmax, fused LN+ELU+split) ----------------
template <int H>
__device__ __forceinline__ void get_alpha(const float* __restrict__ sd,
                                          const float* __restrict__ ar,
                                          int dst, int s, int t, float* a) {
    if (H == 4) {
        float4 sv = *(const float4*)(sd + (size_t)s * 64 + t * 8);
        float4 dv = *(const float4*)(sd + (size_t)dst * 64 + t * 8 + 4);
        float4 av = *(const float4*)(ar + t * 4);
        a[0] = sv.x + dv.x + av.x; a[1] = sv.y + dv.y + av.y;
        a[2] = sv.z + dv.z + av.z; a[3] = sv.w + dv.w + av.w;
    } else {
        a[0] = sd[(size_t)s * 64 + t * 8] + sd[(size_t)dst * 64 + t * 8 + 4] + ar[t];
    }
#pragma unroll
    for (int h = 0; h < H; ++h) a[h] = a[h] > 0.f ? a[h] : 0.2f * a[h];
}

template <int CPL, bool LN>
__global__ __launch_bounds__(256) void k_agg(
    const float* __restrict__ xw, const float* __restrict__ sd,
    const float* __restrict__ ar, const float* __restrict__ bias,
    const float* __restrict__ gamma, const float* __restrict__ beta,
    float* __restrict__ out, __nv_bfloat16* __restrict__ ohi,
    __nv_bfloat16* __restrict__ olo, int N, int xws, int rls) {
    constexpr int H = CPL * 32 / 64;
    constexpr int OUT = CPL * 32;
    __shared__ float walpha[8][32][4];
    int w = (blockIdx.x * blockDim.x + threadIdx.x) >> 5;
    if (w >= N) return;
    int lane = threadIdx.x & 31, wl = threadIdx.x >> 5;
    int hh = (lane * CPL) >> 6;
    int beg = g_rowptr[w], end = g_rowptr[w + 1];

    float mx[H], dn[H];
#pragma unroll
    for (int h = 0; h < H; ++h) { mx[h] = -1e30f; dn[h] = 0.f; }
    for (int e = beg + lane; e < end; e += 32) {
        int2 pe = g_pse[e];
        float a[H];
        get_alpha<H>(sd, ar, w, pe.x, pe.y, a);
#pragma unroll
        for (int h = 0; h < H; ++h) {
            float mn = fmaxf(mx[h], a[h]);
            dn[h] = dn[h] * __expf(mx[h] - mn) + __expf(a[h] - mn);
            mx[h] = mn;
        }
    }
#pragma unroll
    for (int h = 0; h < H; ++h) {
#pragma unroll
        for (int o = 16; o; o >>= 1) {
            float mo = __shfl_xor_sync(0xffffffffu, mx[h], o);
            float dd = __shfl_xor_sync(0xffffffffu, dn[h], o);
            float mn = fmaxf(mx[h], mo);
            dn[h] = dn[h] * __expf(mx[h] - mn) + dd * __expf(mo - mn);
            mx[h] = mn;
        }
        dn[h] = 1.f / dn[h];
    }

    float acc[CPL];
#pragma unroll
    for (int c = 0; c < CPL; ++c) acc[c] = 0.f;

    for (int base = beg; base < end; base += 32) {
        int e = base + lane;
        int cnt = min(32, end - base);
        int sR = 0, tR = 0;
        if (e < end) {
            int2 pe = g_pse[e];
            sR = pe.x; tR = pe.y;
            float a[H];
            get_alpha<H>(sd, ar, w, sR, tR, a);
#pragma unroll
            for (int h = 0; h < H; ++h)
                walpha[wl][lane][h] = __expf(a[h] - mx[h]) * dn[h];
        }
        __syncwarp();
        for (int j = 0; j < cnt; ++j) {
            int s = __shfl_sync(0xffffffffu, sR, j);
            int t = __shfl_sync(0xffffffffu, tR, j);
            float wv = walpha[wl][j][hh];
            const float* p = xw + (size_t)s * xws + t * rls + lane * CPL;
            if (CPL == 8) {
                float4 v0 = *(const float4*)p, v1 = *(const float4*)(p + 4);
                acc[0] += wv * v0.x; acc[1] += wv * v0.y;
                acc[2] += wv * v0.z; acc[3] += wv * v0.w;
                acc[4] += wv * v1.x; acc[5] += wv * v1.y;
                acc[6] += wv * v1.z; acc[7] += wv * v1.w;
            } else {
                float2 v = *(const float2*)p;
                acc[0] += wv * v.x; acc[1] += wv * v.y;
            }
        }
        __syncwarp();
    }

    if (LN) {
        float4 b0 = *(const float4*)(bias + lane * 8);
        float4 b1 = *(const float4*)(bias + lane * 8 + 4);
        acc[0] += b0.x; acc[1] += b0.y; acc[2] += b0.z; acc[3] += b0.w;
        acc[4] += b1.x; acc[5] += b1.y; acc[6] += b1.z; acc[7] += b1.w;
        float s1 = 0.f;
#pragma unroll
        for (int c = 0; c < CPL; ++c) s1 += acc[c];
#pragma unroll
        for (int o = 16; o; o >>= 1) s1 += __shfl_xor_sync(0xffffffffu, s1, o);
        float m = s1 / (float)OUT;
        float s2 = 0.f;
#pragma unroll
        for (int c = 0; c < CPL; ++c) { float d = acc[c] - m; s2 += d * d; }
#pragma unroll
        for (int o = 16; o; o >>= 1) s2 += __shfl_xor_sync(0xffffffffu, s2, o);
        float rstd = rsqrtf(s2 / (float)OUT + 1e-5f);
        float4 gA = *(const float4*)(gamma + lane * 8);
        float4 gB = *(const float4*)(gamma + lane * 8 + 4);
        float4 tA = *(const float4*)(beta + lane * 8);
        float4 tB = *(const float4*)(beta + lane * 8 + 4);
        float gm[8] = {gA.x, gA.y, gA.z, gA.w, gB.x, gB.y, gB.z, gB.w};
        float bt[8] = {tA.x, tA.y, tA.z, tA.w, tB.x, tB.y, tB.z, tB.w};
        __nv_bfloat16 hv[8], lv[8];
#pragma unroll
        for (int c = 0; c < 8; ++c) {
            float y = gm[c] * (acc[c] - m) * rstd + bt[c];
            y = y > 0.f ? y : (expf(y) - 1.f);
            hv[c] = __float2bfloat16(y);
            lv[c] = __float2bfloat16(y - __bfloat162float(hv[c]));
        }
        *(float4*)(ohi + (size_t)w * OUT + lane * 8) = *(float4*)hv;
        *(float4*)(olo + (size_t)w * OUT + lane * 8) = *(float4*)lv;
    } else {
        out[(size_t)w * OUT + lane * 2] = acc[0] + bias[lane * 2];
        out[(size_t)w * OUT + lane * 2 + 1] = acc[1] + bias[lane * 2 + 1];
    }
}

// ---------------- launch ----------------
extern "C" void kernel_launch(void* const* d_in, const int* in_sizes, int n_in,
                              void* d_out, int out_size) {
    const float* x   = (const float*)d_in[0];
    const void*  ei  = d_in[1];
    const void*  et  = d_in[2];
    const float* W0  = (const float*)d_in[3];
    const float* as0 = (const float*)d_in[4];
    const float* ad0 = (const float*)d_in[5];
    const float* ar0 = (const float*)d_in[6];
    const float* bi0 = (const float*)d_in[7];
    const float* W1  = (const float*)d_in[8];
    const float* as1 = (const float*)d_in[9];
    const float* ad1 = (const float*)d_in[10];
    const float* ar1 = (const float*)d_in[11];
    const float* bi1 = (const float*)d_in[12];
    const float* W2  = (const float*)d_in[13];
    const float* as2 = (const float*)d_in[14];
    const float* ad2 = (const float*)d_in[15];
    const float* ar2 = (const float*)d_in[16];
    const float* bi2 = (const float*)d_in[17];
    const float* g0  = (const float*)d_in[18];
    const float* be0 = (const float*)d_in[19];
    const float* g1  = (const float*)d_in[20];
    const float* be1 = (const float*)d_in[21];

    const int N = in_sizes[0] / 128;        // 50000
    const int E = in_sizes[2];              // 800000
    float* out = (float*)d_out;

    float *xw, *sd;
    __nv_bfloat16 *ahi, *alo, *wthi, *wtlo, *wsdthi, *wsdtlo;
    cudaGetSymbolAddress((void**)&xw, g_xw);
    cudaGetSymbolAddress((void**)&sd, g_sd);
    cudaGetSymbolAddress((void**)&ahi, g_ahi);
    cudaGetSymbolAddress((void**)&alo, g_alo);
    cudaGetSymbolAddress((void**)&wthi, g_wthi);
    cudaGetSymbolAddress((void**)&wtlo, g_wtlo);
    cudaGetSymbolAddress((void**)&wsdthi, g_wsdthi);
    cudaGetSymbolAddress((void**)&wsdtlo, g_wsdtlo);

    static int smem_set = 0;
    if (!smem_set) {
        cudaFuncSetAttribute(k_gemm, cudaFuncAttributeMaxDynamicSharedMemorySize,
                             (int)GEMM_SMEM);
        cudaFuncSetAttribute(k_gemm2, cudaFuncAttributeMaxDynamicSharedMemorySize,
                             (int)SMEM2);
        smem_set = 1;
    }

    const int MB = (N + 127) / 128;         // 391
    const int MB2 = (N + 255) / 256;        // 196
    const int EB = (E + 255) / 256;
    const int NB = (N + 255) / 256;
    const int SB = (N + 1023) / 1024;

    // ---- layer 0 dense front (big GEMM early for ncu window) ----
    k_split<<<(N * 128 + 255) / 256, 256>>>(x, ahi, alo, N * 128);
    k_splitW<<<(8 * 128 * 256 + 255) / 256, 256>>>(W0, wthi, wtlo, 128, 256, 8 * 128 * 256);
    k_prep<<<(128 * 64 + 255) / 256, 256>>>(W0, as0, ad0, 128, 4, 64, 256);
    k_gemm2<<<dim3(MB2, 16), 512, SMEM2>>>(ahi, alo, wthi, wtlo, xw, N, 128, 2048);
    k_gemm<<<dim3(MB, 1), 256, GEMM_SMEM>>>(ahi, alo, wsdthi, wsdtlo, sd, N, 128, 64);

    // ---- CSR build ----
    k_detect<<<1, 32>>>((const int*)ei);
    k_zero<<<NB, 256>>>(N);
    k_hist<<<EB, 256>>>(ei, E);
    k_scan1<<<SB, 1024>>>(N);
    k_scan2<<<1, 1>>>(SB);
    k_scan3<<<NB, 256>>>(N, E);
    k_scatter<<<EB, 256>>>(ei, et, E);

    k_agg<8, true><<<(N * 32 + 255) / 256, 256>>>(xw, sd, ar0, bi0, g0, be0,
                                                  nullptr, ahi, alo, N, 2048, 256);

    // ---- layer 1 (K=256) ----
    k_splitW<<<(8 * 256 * 256 + 255) / 256, 256>>>(W1, wthi, wtlo, 256, 256, 8 * 256 * 256);
    k_prep<<<(256 * 64 + 255) / 256, 256>>>(W1, as1, ad1, 256, 4, 64, 256);
    k_gemm<<<dim3(MB, 1), 256, GEMM_SMEM>>>(ahi, alo, wsdthi, wsdtlo, sd, N, 256, 64);
    k_gemm2<<<dim3(MB2, 16), 512, SMEM2>>>(ahi, alo, wthi, wtlo, xw, N, 256, 2048);
    k_agg<8, true><<<(N * 32 + 255) / 256, 256>>>(xw, sd, ar1, bi1, g1, be1,
                                                  nullptr, ahi, alo, N, 2048, 256);

    // ---- layer 2 (K=256, G=512) ----
    k_splitW<<<(8 * 256 * 64 + 255) / 256, 256>>>(W2, wthi, wtlo, 256, 64, 8 * 256 * 64);
    k_prep<<<(256 * 64 + 255) / 256, 256>>>(W2, as2, ad2, 256, 1, 64, 64);
    k_gemm<<<dim3(MB, 1), 256, GEMM_SMEM>>>(ahi, alo, wsdthi, wsdtlo, sd, N, 256, 64);
    k_gemm2<<<dim3(MB2, 4), 512, SMEM2>>>(ahi, alo, wthi, wtlo, xw, N, 256, 512);
    k_agg<2, false><<<(N * 32 + 255) / 256, 256>>>(xw, sd, ar2, bi2, nullptr, nullptr,
                                                   out, nullptr, nullptr, N, 512, 64);
}

// round 14
// speedup vs baseline: 1.4577x; 1.0006x over previous
#include <cuda_runtime.h>
#include <cuda_bf16.h>
#include <cstdint>
#include <cstddef>

// RGAT 3-layer on GB300 (legacy mma.sync; tcgen05 unsupported by harness PTX
// target). bf16 3-term split GEMM is at its HW floor (~46% tensor-pipe ref =
// f32-acc rate); this round recovers serialized non-GEMM time:
//  - sd GEMM fused into xw GEMM as 64 extra B columns (epilogue redirect)
//  - CSR build + W1/W2 prep on a second stream, overlapped with layer-0 GEMM
//  - k_zero -> cudaMemsetAsync

__device__ float g_xw[102400000];           // 50000*2048
__device__ float g_sd[3200000];             // 50000*64
__device__ __nv_bfloat16 g_ahi[12800000];   // 50000*256
__device__ __nv_bfloat16 g_alo[12800000];
__device__ __nv_bfloat16 g_wt0hi[278528];   // 2176*128 (2048 W + 64 sd + 64 pad)
__device__ __nv_bfloat16 g_wt0lo[278528];
__device__ __nv_bfloat16 g_wt1hi[557056];   // 2176*256
__device__ __nv_bfloat16 g_wt1lo[557056];
__device__ __nv_bfloat16 g_wt2hi[163840];   // 640*256 (512 W + 64 sd + 64 pad)
__device__ __nv_bfloat16 g_wt2lo[163840];
__device__ int   g_cnt[50000];
__device__ int   g_rowptr[50001];
__device__ int   g_cur[50000];
__device__ int2  g_pse[800000];             // (src, etype)
__device__ int   g_blk[64];
__device__ int   g_is64;

__device__ __forceinline__ void mma_bf16(float c[4], const uint32_t a[4],
                                         uint32_t b0, uint32_t b1) {
    asm volatile(
        "mma.sync.aligned.m16n8k16.row.col.f32.bf16.bf16.f32 "
        "{%0,%1,%2,%3},{%4,%5,%6,%7},{%8,%9},{%0,%1,%2,%3};"
        : "+f"(c[0]), "+f"(c[1]), "+f"(c[2]), "+f"(c[3])
        : "r"(a[0]), "r"(a[1]), "r"(a[2]), "r"(a[3]), "r"(b0), "r"(b1));
}
__device__ __forceinline__ int ld_idx(const void* p, long long i, int is64) {
    return is64 ? (int)((const long long*)p)[i] : ((const int*)p)[i];
}

// ---------------- dtype detect + CSR build ----------------
__global__ void k_detect(const int* ei) {
    if (threadIdx.x == 0 && blockIdx.x == 0) {
        int z = 0;
        for (int i = 1; i < 64; i += 2) z += (ei[i] == 0);
        g_is64 = (z == 32);
    }
}
__global__ void k_hist(const void* ei, int E) {
    int e = blockIdx.x * blockDim.x + threadIdx.x;
    if (e < E) atomicAdd(&g_cnt[ld_idx(ei, (long long)E + e, g_is64)], 1);
}
__global__ void k_scan1(int N) {
    __shared__ int sh[1024];
    int t = threadIdx.x, i = blockIdx.x * 1024 + t;
    int v = (i < N) ? g_cnt[i] : 0;
    int x = v; sh[t] = x; __syncthreads();
    for (int off = 1; off < 1024; off <<= 1) {
        int add = (t >= off) ? sh[t - off] : 0;
        __syncthreads();
        x += add; sh[t] = x;
        __syncthreads();
    }
    if (i < N) g_rowptr[i] = x - v;
    if (t == 1023) g_blk[blockIdx.x] = x;
}
__global__ void k_scan2(int nb) {
    if (threadIdx.x == 0 && blockIdx.x == 0) {
        int acc = 0;
        for (int b = 0; b < nb; ++b) { int t = g_blk[b]; g_blk[b] = acc; acc += t; }
    }
}
__global__ void k_scan3(int N, int E) {
    int i = blockIdx.x * blockDim.x + threadIdx.x;
    if (i < N) {
        int v = g_rowptr[i] + g_blk[i >> 10];
        g_rowptr[i] = v; g_cur[i] = v;
    }
    if (i == 0) g_rowptr[N] = E;
}
__global__ void k_scatter(const void* ei, const void* et, int E) {
    int e = blockIdx.x * blockDim.x + threadIdx.x;
    if (e >= E) return;
    int is64 = g_is64;
    int s = ld_idx(ei, e, is64);
    int d = ld_idx(ei, (long long)E + e, is64);
    int t = ld_idx(et, e, is64);
    int pos = atomicAdd(&g_cur[d], 1);
    g_pse[pos] = make_int2(s, t);
}

// ---------------- hi/lo splits ----------------
__global__ void k_split(const float* __restrict__ a, __nv_bfloat16* __restrict__ hi,
                        __nv_bfloat16* __restrict__ lo, int n) {
    int i = blockIdx.x * blockDim.x + threadIdx.x;
    if (i >= n) return;
    float x = a[i];
    __nv_bfloat16 h = __float2bfloat16(x);
    hi[i] = h;
    lo[i] = __float2bfloat16(x - __bfloat162float(h));
}
// W[r][k][n] -> WT[(r*Ntot+n)*K + k] hi/lo (into padded buffer)
__global__ void k_splitW(const float* __restrict__ W, __nv_bfloat16* __restrict__ hi,
                         __nv_bfloat16* __restrict__ lo, int K, int Ntot, int total) {
    int i = blockIdx.x * blockDim.x + threadIdx.x;
    if (i >= total) return;
    int k = i % K;
    int rn = i / K;
    int n = rn % Ntot;
    int r = rn / Ntot;
    float x = W[((size_t)r * K + k) * Ntot + n];
    __nv_bfloat16 h = __float2bfloat16(x);
    hi[i] = h;
    lo[i] = __float2bfloat16(x - __bfloat162float(h));
}

// ---------------- fold attention vectors into cols [Gxw, Gxw+64) ----------------
__global__ void k_prep(const float* __restrict__ W, const float* __restrict__ as_,
                       const float* __restrict__ ad_, __nv_bfloat16* __restrict__ wHi,
                       __nv_bfloat16* __restrict__ wLo, int K, int H, int C, int Wn,
                       int Gxw) {
    int t = blockIdx.x * blockDim.x + threadIdx.x;
    if (t >= K * 64) return;
    int col = t & 63, k = t >> 6;
    int r = col >> 3, q = col & 7, h = q & 3;
    float acc = 0.f;
    if (h < H) {
        const float* av = ((q & 4) ? ad_ : as_) + h * C;
        const float* wp = W + ((size_t)r * K + k) * Wn + h * C;
        for (int c = 0; c < C; ++c) acc += wp[c] * av[c];
    }
    __nv_bfloat16 hb = __float2bfloat16(acc);
    size_t o = (size_t)(Gxw + col) * K + k;
    wHi[o] = hb;
    wLo[o] = __float2bfloat16(acc - __bfloat162float(hb));
}

// ============ GEMM: BM=256, BN=128, 512 threads, sd columns fused ============
#define ST2 15360
#define SMEM2 (size_t)(2 * ST2 * 4)

__device__ __forceinline__ void load_tile2(
    uint32_t* base, int tid, int m0, int M, int K, int kof, int n0,
    const __nv_bfloat16* Ahi, const __nv_bfloat16* Alo,
    const __nv_bfloat16* Bhi, const __nv_bfloat16* Blo) {
#pragma unroll
    for (int i = 0; i < 4; ++i) {
        int idx = tid + i * 512;
        int half = idx >> 10, rem = idx & 1023;
        int row = rem >> 2, ch = rem & 3;
        int gr = m0 + row;
        const __nv_bfloat16* p = (half ? Alo : Ahi) + (size_t)(gr < M ? gr : 0) * K + kof + ch * 8;
        uint32_t dst = (uint32_t)__cvta_generic_to_shared(base + half * 5120 + row * 20 + ch * 4);
        int sz = (gr < M) ? 16 : 0;
        asm volatile("cp.async.cg.shared.global [%0], [%1], 16, %2;"
                     :: "r"(dst), "l"(p), "r"(sz));
    }
#pragma unroll
    for (int i = 0; i < 2; ++i) {
        int idx = tid + i * 512;
        int half = idx >> 9, rem = idx & 511;
        int col = rem >> 2, ch = rem & 3;
        const __nv_bfloat16* p = (half ? Blo : Bhi) + (size_t)(n0 + col) * K + kof + ch * 8;
        uint32_t dst = (uint32_t)__cvta_generic_to_shared(base + 10240 + half * 2560 + col * 20 + ch * 4);
        asm volatile("cp.async.cg.shared.global [%0], [%1], 16;" :: "r"(dst), "l"(p));
    }
    asm volatile("cp.async.commit_group;");
}

__global__ __launch_bounds__(512, 1) void k_gemm2(
    const __nv_bfloat16* __restrict__ Ahi, const __nv_bfloat16* __restrict__ Alo,
    const __nv_bfloat16* __restrict__ Bhi, const __nv_bfloat16* __restrict__ Blo,
    float* __restrict__ C, float* __restrict__ SD,
    int M, int K, int crs, int Gxw) {
    extern __shared__ uint32_t sm[];
    const int tid = threadIdx.x;
    const int m0 = blockIdx.x * 256;
    const int n0 = blockIdx.y * 128;

    const int lane = tid & 31, wid = tid >> 5;
    const int gid = lane >> 2, tig = lane & 3;
    const int m_off = (wid & 7) * 32, n_off = (wid >> 3) * 64;

    float acc[2][8][4];
#pragma unroll
    for (int f = 0; f < 2; ++f)
#pragma unroll
        for (int n = 0; n < 8; ++n)
#pragma unroll
            for (int q = 0; q < 4; ++q) acc[f][n][q] = 0.f;

    const int nkt = K >> 5;
    load_tile2(sm, tid, m0, M, K, 0, n0, Ahi, Alo, Bhi, Blo);

    for (int kt = 0; kt < nkt; ++kt) {
        if (kt + 1 < nkt) {
            load_tile2(sm + ((kt + 1) & 1) * ST2, tid, m0, M, K, (kt + 1) * 32, n0,
                       Ahi, Alo, Bhi, Blo);
            asm volatile("cp.async.wait_group 1;");
        } else {
            asm volatile("cp.async.wait_group 0;");
        }
        __syncthreads();
        const uint32_t* base = sm + (kt & 1) * ST2;
        const uint32_t* AsH = base;
        const uint32_t* AsL = base + 5120;
        const uint32_t* BsH = base + 10240;
        const uint32_t* BsL = base + 12800;
#pragma unroll
        for (int ks = 0; ks < 2; ++ks) {
            uint32_t aH[2][4], aL[2][4];
#pragma unroll
            for (int f = 0; f < 2; ++f) {
                int ro = (m_off + f * 16 + gid) * 20 + ks * 8 + tig;
                aH[f][0] = AsH[ro];           aH[f][1] = AsH[ro + 160];
                aH[f][2] = AsH[ro + 4];       aH[f][3] = AsH[ro + 164];
                aL[f][0] = AsL[ro];           aL[f][1] = AsL[ro + 160];
                aL[f][2] = AsL[ro + 4];       aL[f][3] = AsL[ro + 164];
            }
#pragma unroll
            for (int hf = 0; hf < 2; ++hf) {
                uint32_t bh[4][2], bl[4][2];
#pragma unroll
                for (int j = 0; j < 4; ++j) {
                    int bo = (n_off + (hf * 4 + j) * 8 + gid) * 20 + ks * 8 + tig;
                    bh[j][0] = BsH[bo]; bh[j][1] = BsH[bo + 4];
                    bl[j][0] = BsL[bo]; bl[j][1] = BsL[bo + 4];
                }
#pragma unroll
                for (int j = 0; j < 4; ++j) {
                    mma_bf16(acc[0][hf * 4 + j], aH[0], bh[j][0], bh[j][1]);
                    mma_bf16(acc[1][hf * 4 + j], aH[1], bh[j][0], bh[j][1]);
                }
#pragma unroll
                for (int j = 0; j < 4; ++j) {
                    mma_bf16(acc[0][hf * 4 + j], aH[0], bl[j][0], bl[j][1]);
                    mma_bf16(acc[1][hf * 4 + j], aH[1], bl[j][0], bl[j][1]);
                }
#pragma unroll
                for (int j = 0; j < 4; ++j) {
                    mma_bf16(acc[0][hf * 4 + j], aL[0], bh[j][0], bh[j][1]);
                    mma_bf16(acc[1][hf * 4 + j], aL[1], bh[j][0], bh[j][1]);
                }
            }
        }
        __syncthreads();
    }
    // epilogue: cols < Gxw -> C; [Gxw, Gxw+64) -> SD; rest padded (skip)
#pragma unroll
    for (int f = 0; f < 2; ++f) {
        int row = m0 + m_off + f * 16 + gid;
#pragma unroll
        for (int nf = 0; nf < 8; ++nf) {
            int c = n0 + n_off + nf * 8 + 2 * tig;
            float2 v0 = make_float2(acc[f][nf][0], acc[f][nf][1]);
            float2 v1 = make_float2(acc[f][nf][2], acc[f][nf][3]);
            if (c < Gxw) {
                if (row < M) *(float2*)(C + (size_t)row * crs + c) = v0;
                if (row + 8 < M) *(float2*)(C + (size_t)(row + 8) * crs + c) = v1;
            } else if (c < Gxw + 64) {
                int cc = c - Gxw;
                if (row < M) *(float2*)(SD + (size_t)row * 64 + cc) = v0;
                if (row + 8 < M) *(float2*)(SD + (size_t)(row + 8) * 64 + cc) = v1;
            }
        }
    }
}

// ---------------- aggregation (online softmax, fused LN+ELU+split) ----------------
template <int H>
__device__ __forceinline__ void get_alpha(const float* __restrict__ sd,
                                          const float* __restrict__ ar,
                                          int dst, int s, int t, float* a) {
    if (H == 4) {
        float4 sv = *(const float4*)(sd + (size_t)s * 64 + t * 8);
        float4 dv = *(const float4*)(sd + (size_t)dst * 64 + t * 8 + 4);
        float4 av = *(const float4*)(ar + t * 4);
        a[0] = sv.x + dv.x + av.x; a[1] = sv.y + dv.y + av.y;
        a[2] = sv.z + dv.z + av.z; a[3] = sv.w + dv.w + av.w;
    } else {
        a[0] = sd[(size_t)s * 64 + t * 8] + sd[(size_t)dst * 64 + t * 8 + 4] + ar[t];
    }
#pragma unroll
    for (int h = 0; h < H; ++h) a[h] = a[h] > 0.f ? a[h] : 0.2f * a[h];
}

template <int CPL, bool LN>
__global__ __launch_bounds__(256) void k_agg(
    const float* __restrict__ xw, const float* __restrict__ sd,
    const float* __restrict__ ar, const float* __restrict__ bias,
    const float* __restrict__ gamma, const float* __restrict__ beta,
    float* __restrict__ out, __nv_bfloat16* __restrict__ ohi,
    __nv_bfloat16* __restrict__ olo, int N, int xws, int rls) {
    constexpr int H = CPL * 32 / 64;
    constexpr int OUT = CPL * 32;
    __shared__ float walpha[8][32][4];
    int w = (blockIdx.x * blockDim.x + threadIdx.x) >> 5;
    if (w >= N) return;
    int lane = threadIdx.x & 31, wl = threadIdx.x >> 5;
    int hh = (lane * CPL) >> 6;
    int beg = g_rowptr[w], end = g_rowptr[w + 1];

    float mx[H], dn[H];
#pragma unroll
    for (int h = 0; h < H; ++h) { mx[h] = -1e30f; dn[h] = 0.f; }
    for (int e = beg + lane; e < end; e += 32) {
        int2 pe = g_pse[e];
        float a[H];
        get_alpha<H>(sd, ar, w, pe.x, pe.y, a);
#pragma unroll
        for (int h = 0; h < H; ++h) {
            float mn = fmaxf(mx[h], a[h]);
            dn[h] = dn[h] * __expf(mx[h] - mn) + __expf(a[h] - mn);
            mx[h] = mn;
        }
    }
#pragma unroll
    for (int h = 0; h < H; ++h) {
#pragma unroll
        for (int o = 16; o; o >>= 1) {
            float mo = __shfl_xor_sync(0xffffffffu, mx[h], o);
            float dd = __shfl_xor_sync(0xffffffffu, dn[h], o);
            float mn = fmaxf(mx[h], mo);
            dn[h] = dn[h] * __expf(mx[h] - mn) + dd * __expf(mo - mn);
            mx[h] = mn;
        }
        dn[h] = 1.f / dn[h];
    }

    float acc[CPL];
#pragma unroll
    for (int c = 0; c < CPL; ++c) acc[c] = 0.f;

    for (int base = beg; base < end; base += 32) {
        int e = base + lane;
        int cnt = min(32, end - base);
        int sR = 0, tR = 0;
        if (e < end) {
            int2 pe = g_pse[e];
            sR = pe.x; tR = pe.y;
            float a[H];
            get_alpha<H>(sd, ar, w, sR, tR, a);
#pragma unroll
            for (int h = 0; h < H; ++h)
                walpha[wl][lane][h] = __expf(a[h] - mx[h]) * dn[h];
        }
        __syncwarp();
        for (int j = 0; j < cnt; ++j) {
            int s = __shfl_sync(0xffffffffu, sR, j);
            int t = __shfl_sync(0xffffffffu, tR, j);
            float wv = walpha[wl][j][hh];
            const float* p = xw + (size_t)s * xws + t * rls + lane * CPL;
            if (CPL == 8) {
                float4 v0 = *(const float4*)p, v1 = *(const float4*)(p + 4);
                acc[0] += wv * v0.x; acc[1] += wv * v0.y;
                acc[2] += wv * v0.z; acc[3] += wv * v0.w;
                acc[4] += wv * v1.x; acc[5] += wv * v1.y;
                acc[6] += wv * v1.z; acc[7] += wv * v1.w;
            } else {
                float2 v = *(const float2*)p;
                acc[0] += wv * v.x; acc[1] += wv * v.y;
            }
        }
        __syncwarp();
    }

    if (LN) {
        float4 b0 = *(const float4*)(bias + lane * 8);
        float4 b1 = *(const float4*)(bias + lane * 8 + 4);
        acc[0] += b0.x; acc[1] += b0.y; acc[2] += b0.z; acc[3] += b0.w;
        acc[4] += b1.x; acc[5] += b1.y; acc[6] += b1.z; acc[7] += b1.w;
        float s1 = 0.f;
#pragma unroll
        for (int c = 0; c < CPL; ++c) s1 += acc[c];
#pragma unroll
        for (int o = 16; o; o >>= 1) s1 += __shfl_xor_sync(0xffffffffu, s1, o);
        float m = s1 / (float)OUT;
        float s2 = 0.f;
#pragma unroll
        for (int c = 0; c < CPL; ++c) { float d = acc[c] - m; s2 += d * d; }
#pragma unroll
        for (int o = 16; o; o >>= 1) s2 += __shfl_xor_sync(0xffffffffu, s2, o);
        float rstd = rsqrtf(s2 / (float)OUT + 1e-5f);
        float4 gA = *(const float4*)(gamma + lane * 8);
        float4 gB = *(const float4*)(gamma + lane * 8 + 4);
        float4 tA = *(const float4*)(beta + lane * 8);
        float4 tB = *(const float4*)(beta + lane * 8 + 4);
        float gm[8] = {gA.x, gA.y, gA.z, gA.w, gB.x, gB.y, gB.z, gB.w};
        float bt[8] = {tA.x, tA.y, tA.z, tA.w, tB.x, tB.y, tB.z, tB.w};
        __nv_bfloat16 hv[8], lv[8];
#pragma unroll
        for (int c = 0; c < 8; ++c) {
            float y = gm[c] * (acc[c] - m) * rstd + bt[c];
            y = y > 0.f ? y : (expf(y) - 1.f);
            hv[c] = __float2bfloat16(y);
            lv[c] = __float2bfloat16(y - __bfloat162float(hv[c]));
        }
        *(float4*)(ohi + (size_t)w * OUT + lane * 8) = *(float4*)hv;
        *(float4*)(olo + (size_t)w * OUT + lane * 8) = *(float4*)lv;
    } else {
        out[(size_t)w * OUT + lane * 2] = acc[0] + bias[lane * 2];
        out[(size_t)w * OUT + lane * 2 + 1] = acc[1] + bias[lane * 2 + 1];
    }
}

// ---------------- launch ----------------
extern "C" void kernel_launch(void* const* d_in, const int* in_sizes, int n_in,
                              void* d_out, int out_size) {
    const float* x   = (const float*)d_in[0];
    const void*  ei  = d_in[1];
    const void*  et  = d_in[2];
    const float* W0  = (const float*)d_in[3];
    const float* as0 = (const float*)d_in[4];
    const float* ad0 = (const float*)d_in[5];
    const float* ar0 = (const float*)d_in[6];
    const float* bi0 = (const float*)d_in[7];
    const float* W1  = (const float*)d_in[8];
    const float* as1 = (const float*)d_in[9];
    const float* ad1 = (const float*)d_in[10];
    const float* ar1 = (const float*)d_in[11];
    const float* bi1 = (const float*)d_in[12];
    const float* W2  = (const float*)d_in[13];
    const float* as2 = (const float*)d_in[14];
    const float* ad2 = (const float*)d_in[15];
    const float* ar2 = (const float*)d_in[16];
    const float* bi2 = (const float*)d_in[17];
    const float* bi2u = bi2; (void)bi2u;
    const float* g0  = (const float*)d_in[18];
    const float* be0 = (const float*)d_in[19];
    const float* g1  = (const float*)d_in[20];
    const float* be1 = (const float*)d_in[21];

    const int N = in_sizes[0] / 128;        // 50000
    const int E = in_sizes[2];              // 800000
    float* out = (float*)d_out;

    float *xw, *sd;
    __nv_bfloat16 *ahi, *alo, *wt0h, *wt0l, *wt1h, *wt1l, *wt2h, *wt2l;
    int* cnt;
    cudaGetSymbolAddress((void**)&xw, g_xw);
    cudaGetSymbolAddress((void**)&sd, g_sd);
    cudaGetSymbolAddress((void**)&ahi, g_ahi);
    cudaGetSymbolAddress((void**)&alo, g_alo);
    cudaGetSymbolAddress((void**)&wt0h, g_wt0hi);
    cudaGetSymbolAddress((void**)&wt0l, g_wt0lo);
    cudaGetSymbolAddress((void**)&wt1h, g_wt1hi);
    cudaGetSymbolAddress((void**)&wt1l, g_wt1lo);
    cudaGetSymbolAddress((void**)&wt2h, g_wt2hi);
    cudaGetSymbolAddress((void**)&wt2l, g_wt2lo);
    cudaGetSymbolAddress((void**)&cnt, g_cnt);

    static cudaStream_t s1;
    static cudaEvent_t ev0, evB;
    static int init_done = 0;
    if (!init_done) {
        cudaFuncSetAttribute(k_gemm2, cudaFuncAttributeMaxDynamicSharedMemorySize,
                             (int)SMEM2);
        cudaStreamCreateWithFlags(&s1, cudaStreamNonBlocking);
        cudaEventCreateWithFlags(&ev0, cudaEventDisableTiming);
        cudaEventCreateWithFlags(&evB, cudaEventDisableTiming);
        init_done = 1;
    }

    const int MB2 = (N + 255) / 256;        // 196
    const int EB = (E + 255) / 256;
    const int NB = (N + 255) / 256;
    const int SB = (N + 1023) / 1024;

    // -------- fork: independent chain on s1 (CSR + W1/W2 prep) --------
    cudaEventRecord(ev0, 0);
    cudaStreamWaitEvent(s1, ev0, 0);

    k_detect<<<1, 32, 0, s1>>>((const int*)ei);
    cudaMemsetAsync(cnt, 0, (size_t)N * 4, s1);
    k_hist<<<EB, 256, 0, s1>>>(ei, E);
    k_scan1<<<SB, 1024, 0, s1>>>(N);
    k_scan2<<<1, 1, 0, s1>>>(SB);
    k_scan3<<<NB, 256, 0, s1>>>(N, E);
    k_scatter<<<EB, 256, 0, s1>>>(ei, et, E);
    // W1 -> wt1 (Gxw=2048, K=256), pad tail [2112,2176)
    k_splitW<<<(8 * 256 * 256 + 255) / 256, 256, 0, s1>>>(W1, wt1h, wt1l, 256, 256, 8 * 256 * 256);
    k_prep<<<(256 * 64 + 255) / 256, 256, 0, s1>>>(W1, as1, ad1, wt1h, wt1l, 256, 4, 64, 256, 2048);
    cudaMemsetAsync(wt1h + 2112 * 256, 0, (size_t)64 * 256 * 2, s1);
    cudaMemsetAsync(wt1l + 2112 * 256, 0, (size_t)64 * 256 * 2, s1);
    // W2 -> wt2 (Gxw=512, K=256), pad tail [576,640)
    k_splitW<<<(8 * 64 * 256 + 255) / 256, 256, 0, s1>>>(W2, wt2h, wt2l, 256, 64, 8 * 64 * 256);
    k_prep<<<(256 * 64 + 255) / 256, 256, 0, s1>>>(W2, as2, ad2, wt2h, wt2l, 256, 1, 64, 64, 512);
    cudaMemsetAsync(wt2h + 576 * 256, 0, (size_t)64 * 256 * 2, s1);
    cudaMemsetAsync(wt2l + 576 * 256, 0, (size_t)64 * 256 * 2, s1);
    cudaEventRecord(evB, s1);

    // -------- main stream: layer 0 dense --------
    k_split<<<(N * 128 + 255) / 256, 256>>>(x, ahi, alo, N * 128);
    k_splitW<<<(8 * 128 * 256 + 255) / 256, 256>>>(W0, wt0h, wt0l, 128, 256, 8 * 128 * 256);
    k_prep<<<(128 * 64 + 255) / 256, 256>>>(W0, as0, ad0, wt0h, wt0l, 128, 4, 64, 256, 2048);
    cudaMemsetAsync(wt0h + 2112 * 128, 0, (size_t)64 * 128 * 2, 0);
    cudaMemsetAsync(wt0l + 2112 * 128, 0, (size_t)64 * 128 * 2, 0);
    k_gemm2<<<dim3(MB2, 17), 512, SMEM2>>>(ahi, alo, wt0h, wt0l, xw, sd, N, 128, 2048, 2048);

    // join: agg0 needs CSR (and later layers need wt1/wt2)
    cudaStreamWaitEvent(0, evB, 0);
    k_agg<8, true><<<(N * 32 + 255) / 256, 256>>>(xw, sd, ar0, bi0, g0, be0,
                                                  nullptr, ahi, alo, N, 2048, 256);

    // -------- layer 1 --------
    k_gemm2<<<dim3(MB2, 17), 512, SMEM2>>>(ahi, alo, wt1h, wt1l, xw, sd, N, 256, 2048, 2048);
    k_agg<8, true><<<(N * 32 + 255) / 256, 256>>>(xw, sd, ar1, bi1, g1, be1,
                                                  nullptr, ahi, alo, N, 2048, 256);

    // -------- layer 2 --------
    k_gemm2<<<dim3(MB2, 5), 512, SMEM2>>>(ahi, alo, wt2h, wt2l, xw, sd, N, 256, 512, 512);
    k_agg<2, false><<<(N * 32 + 255) / 256, 256>>>(xw, sd, ar2, bi2, nullptr, nullptr,
                                                   out, nullptr, nullptr, N, 512, 64);
}